// round 2
// baseline (speedup 1.0000x reference)
#include <cuda_runtime.h>
#include <math.h>

#define Nn 6000
#define Ee 120000
#define Dd 128
#define Hh 4
#define Cc 384

// ---------------- scratch (device globals; no allocation allowed) ----------------
// All float arrays 16B-aligned: they are read/written with float4 (LDG.128/STG.128),
// and a misaligned 128-bit access traps on sm_103a.
__device__ __align__(16) float g_nodes[Nn * Dd];
__device__ __align__(16) float g_eattr[Ee * Dd];
__device__ __align__(16) float g_nupd[Ee * Dd];
__device__ __align__(16) float g_nupd2[Ee * Dd];
__device__ __align__(16) float g_scores[Ee * Hh];
__device__ __align__(16) float g_agg[Nn * Hh * Dd];
__device__ __align__(16) float g_upd[Nn * Dd];
__device__ __align__(16) float g_hid[Nn * 4 * Dd];
__device__ __align__(16) float g_dense[Nn * Dd];
__device__ int g_cnt[Nn];
__device__ int g_off[Nn + 1];
__device__ int g_cur[Nn];
__device__ int g_csr[Ee];

__device__ __forceinline__ float gelu_f(float x) {
    return 0.5f * x * (1.0f + erff(x * 0.70710678118654752f));
}

// ---------------- generic SGEMM: C = act(A @ B + bias) ----------------
// act: 0 none, 1 gelu, 2 score-mode (lrelu then dot with aA, warp-reduced -> scores)
// featMode: A row m is virtual [nodes[src[m]], nodes[snk[m]], eattr[m]] (K=384)
__global__ void __launch_bounds__(256) gemm_k(
    int M, int K,
    const float* __restrict__ A,
    const float* __restrict__ Bmat, int Nld, long long bStrideZ,
    const float* __restrict__ bias, int biasStrideZ,
    float* __restrict__ Cout, int ldc, long long cColStrideZ,
    int act, int featMode,
    const float* __restrict__ nodes,
    const float* __restrict__ eattr,
    const int* __restrict__ srcI,
    const int* __restrict__ snkI,
    const float* __restrict__ aAv,
    const float* __restrict__ aAb)
{
    __shared__ float As[64][33];
    __shared__ float Bs[32][128];
    const int z = blockIdx.z;
    const float* B = Bmat + (long long)z * bStrideZ;
    const float* bi = bias + (long long)z * biasStrideZ;

    int tid = threadIdx.x;
    int m0 = blockIdx.y * 64;
    int n0 = blockIdx.x * 128;
    int rg = tid >> 5;          // warp id: row group 0..7
    int lane = tid & 31;
    int row0 = rg * 8;
    int col0 = lane * 4;

    float acc[8][4];
#pragma unroll
    for (int i = 0; i < 8; i++)
#pragma unroll
        for (int j = 0; j < 4; j++) acc[i][j] = 0.f;

    for (int k0 = 0; k0 < K; k0 += 32) {
        // A tile: 64 x 32
#pragma unroll
        for (int it = 0; it < 2; ++it) {
            int idx = tid + it * 256;
            int r = idx >> 3;
            int c4 = (idx & 7) << 2;
            int m = m0 + r;
            float4 v = make_float4(0.f, 0.f, 0.f, 0.f);
            if (m < M) {
                int kg = k0 + c4;
                const float* p;
                if (!featMode) p = A + (long long)m * K + kg;
                else if (kg < 128) p = nodes + (long long)srcI[m] * 128 + kg;
                else if (kg < 256) p = nodes + (long long)snkI[m] * 128 + (kg - 128);
                else p = eattr + (long long)m * 128 + (kg - 256);
                v = *(const float4*)p;
            }
            As[r][c4] = v.x; As[r][c4 + 1] = v.y; As[r][c4 + 2] = v.z; As[r][c4 + 3] = v.w;
        }
        // B tile: 32 x 128
#pragma unroll
        for (int it = 0; it < 4; ++it) {
            int idx = tid + it * 256;
            int r = idx >> 5;
            int c4 = (idx & 31) << 2;
            *(float4*)&Bs[r][c4] = *(const float4*)(B + (long long)(k0 + r) * Nld + n0 + c4);
        }
        __syncthreads();
#pragma unroll
        for (int k = 0; k < 32; k++) {
            float b4[4];
            *(float4*)b4 = *(const float4*)&Bs[k][col0];
#pragma unroll
            for (int i = 0; i < 8; i++) {
                float a = As[row0 + i][k];
                acc[i][0] += a * b4[0];
                acc[i][1] += a * b4[1];
                acc[i][2] += a * b4[2];
                acc[i][3] += a * b4[3];
            }
        }
        __syncthreads();
    }

    if (act == 2) {
        // attention score epilogue: n0 == 0, 128 cols per head z
        const float* av = aAv + z * 128;
#pragma unroll
        for (int i = 0; i < 8; i++) {
            float p = 0.f;
#pragma unroll
            for (int j = 0; j < 4; j++) {
                int n = col0 + j;
                float v = acc[i][j] + bi[n];
                v = v > 0.f ? v : 0.2f * v;   // LeakyReLU(0.2)
                p += v * av[n];
            }
#pragma unroll
            for (int o = 16; o; o >>= 1) p += __shfl_xor_sync(0xffffffffu, p, o);
            int m = m0 + row0 + i;
            if (lane == 0 && m < M) Cout[(long long)m * 4 + z] = p + aAb[z];
        }
        return;
    }

    float* Cp = Cout + (long long)z * cColStrideZ;
#pragma unroll
    for (int i = 0; i < 8; i++) {
        int m = m0 + row0 + i;
        if (m >= M) continue;
#pragma unroll
        for (int j = 0; j < 4; j++) {
            int n = n0 + col0 + j;
            float v = acc[i][j] + bi[n];
            if (act == 1) v = gelu_f(v);
            Cp[(long long)m * ldc + n] = v;
        }
    }
}

// ---------------- setup kernels ----------------
__global__ void embed_k(const int* __restrict__ seq, const float* __restrict__ emb) {
    int i = blockIdx.x * 256 + threadIdx.x;
    if (i < Nn * 128) {
        int nidx = i >> 7, d = i & 127;
        g_nodes[i] = emb[seq[nidx] * 128 + d];
    }
}

__global__ void rbf_k(const float* __restrict__ dist, const float* __restrict__ W,
                      const float* __restrict__ b) {
    __shared__ float r[16];
    int e = blockIdx.x;
    int t = threadIdx.x;
    if (t < 16) {
        float mu = 2.0f + (20.0f / 15.0f) * (float)t;   // linspace(2,22,16)
        float x = (dist[e] - mu) * (1.0f / 1.25f);      // sig = 20/16
        r[t] = expf(-x * x) + 1e-8f;
    }
    __syncthreads();
    float s = b[t];
#pragma unroll
    for (int j = 0; j < 16; j++) s += r[j] * W[j * 128 + t];
    g_eattr[(long long)e * 128 + t] = s;
}

// ---------------- CSR build ----------------
__global__ void zero_cnt_k() {
    int i = blockIdx.x * 256 + threadIdx.x;
    if (i < Nn) g_cnt[i] = 0;
}
__global__ void count_k(const int* __restrict__ snk) {
    int e = blockIdx.x * 256 + threadIdx.x;
    if (e < Ee) atomicAdd(&g_cnt[snk[e]], 1);
}
__global__ void __launch_bounds__(1024) scan_k() {
    __shared__ int s[1024];
    int t = threadIdx.x;
    const int CH = (Nn + 1023) / 1024;
    int st = t * CH;
    int en = st + CH; if (en > Nn) en = Nn; if (st > Nn) st = Nn;
    int loc = 0;
    for (int i = st; i < en; i++) loc += g_cnt[i];
    s[t] = loc;
    __syncthreads();
    for (int d = 1; d < 1024; d <<= 1) {
        int v = (t >= d) ? s[t - d] : 0;
        __syncthreads();
        s[t] += v;
        __syncthreads();
    }
    int run = (t == 0) ? 0 : s[t - 1];
    for (int i = st; i < en; i++) {
        g_off[i] = run; g_cur[i] = run; run += g_cnt[i];
    }
    if (t == 1023) g_off[Nn] = s[1023];
}
__global__ void place_k(const int* __restrict__ snk) {
    int e = blockIdx.x * 256 + threadIdx.x;
    if (e < Ee) {
        int p = atomicAdd(&g_cur[snk[e]], 1);
        g_csr[p] = e;
    }
}

// ---------------- per-node softmax + aggregation ----------------
__global__ void __launch_bounds__(128) agg_k() {
    __shared__ float red[4][128];
    int n = blockIdx.x, t = threadIdx.x;
    int beg = g_off[n], end = g_off[n + 1];
    const float4* sc4 = (const float4*)g_scores;

    float mx[4] = {-1e30f, -1e30f, -1e30f, -1e30f};
    for (int i = beg + t; i < end; i += 128) {
        float4 s = sc4[g_csr[i]];
        mx[0] = fmaxf(mx[0], s.x); mx[1] = fmaxf(mx[1], s.y);
        mx[2] = fmaxf(mx[2], s.z); mx[3] = fmaxf(mx[3], s.w);
    }
#pragma unroll
    for (int h = 0; h < 4; h++) red[h][t] = mx[h];
    __syncthreads();
    for (int s = 64; s > 0; s >>= 1) {
        if (t < s)
#pragma unroll
            for (int h = 0; h < 4; h++) red[h][t] = fmaxf(red[h][t], red[h][t + s]);
        __syncthreads();
    }
    float mxf[4];
#pragma unroll
    for (int h = 0; h < 4; h++) mxf[h] = red[h][0];
    __syncthreads();

    float sm[4] = {0.f, 0.f, 0.f, 0.f};
    for (int i = beg + t; i < end; i += 128) {
        float4 s = sc4[g_csr[i]];
        sm[0] += expf(s.x - mxf[0]) + 1e-12f;
        sm[1] += expf(s.y - mxf[1]) + 1e-12f;
        sm[2] += expf(s.z - mxf[2]) + 1e-12f;
        sm[3] += expf(s.w - mxf[3]) + 1e-12f;
    }
#pragma unroll
    for (int h = 0; h < 4; h++) red[h][t] = sm[h];
    __syncthreads();
    for (int s = 64; s > 0; s >>= 1) {
        if (t < s)
#pragma unroll
            for (int h = 0; h < 4; h++) red[h][t] += red[h][t + s];
        __syncthreads();
    }
    float nrm[4];
#pragma unroll
    for (int h = 0; h < 4; h++) nrm[h] = red[h][0];

    float acc[4] = {0.f, 0.f, 0.f, 0.f};
    for (int i = beg; i < end; i++) {
        int e = g_csr[i];
        float4 s = sc4[e];
        float a0 = expf(s.x - mxf[0]) / nrm[0];
        float a1 = expf(s.y - mxf[1]) / nrm[1];
        float a2 = expf(s.z - mxf[2]) / nrm[2];
        float a3 = expf(s.w - mxf[3]) / nrm[3];
        float v = g_nupd[(long long)e * 128 + t];
        acc[0] += a0 * v; acc[1] += a1 * v; acc[2] += a2 * v; acc[3] += a3 * v;
    }
    long long base = (long long)n * 512;
#pragma unroll
    for (int h = 0; h < 4; h++) g_agg[base + h * 128 + t] = acc[h];
}

// ---------------- LayerNorm: out = LN(a + r) * g + b ----------------
__global__ void __launch_bounds__(128) ln_k(const float* __restrict__ a,
                                            const float* __restrict__ r,
                                            const float* __restrict__ g,
                                            const float* __restrict__ b,
                                            float* __restrict__ out) {
    int row = blockIdx.x, t = threadIdx.x;
    __shared__ float sh[8];
    long long base = (long long)row * 128;
    float x = a[base + t] + r[base + t];
    float s = x;
#pragma unroll
    for (int o = 16; o; o >>= 1) s += __shfl_xor_sync(0xffffffffu, s, o);
    if ((t & 31) == 0) sh[t >> 5] = s;
    __syncthreads();
    float mean = (sh[0] + sh[1] + sh[2] + sh[3]) * (1.0f / 128.0f);
    float d = x - mean;
    float v = d * d;
#pragma unroll
    for (int o = 16; o; o >>= 1) v += __shfl_xor_sync(0xffffffffu, v, o);
    if ((t & 31) == 0) sh[4 + (t >> 5)] = v;
    __syncthreads();
    float var = (sh[4] + sh[5] + sh[6] + sh[7]) * (1.0f / 128.0f);
    out[base + t] = d * rsqrtf(var + 1e-5f) * g[t] + b[t];
}

// ---------------- copy out ----------------
__global__ void out_k(float* __restrict__ out) {
    long long i = (long long)blockIdx.x * 256 + threadIdx.x;
    const long long nTot = (long long)Nn * 128;
    const long long tot = nTot + (long long)Ee * 128;
    if (i < nTot) out[i] = g_nodes[i];
    else if (i < tot) out[i] = g_eattr[i - nTot];
}

// ---------------- host ----------------
extern "C" void kernel_launch(void* const* d_in, const int* in_sizes, int n_in,
                              void* d_out, int out_size) {
    const int* seq = (const int*)d_in[0];
    const int* eidx = (const int*)d_in[1];
    const int* srcI = eidx;
    const int* snkI = eidx + Ee;
    const float* dist = (const float*)d_in[2];
    const float* seq_embed = (const float*)d_in[3];
    const float* edge_lin_W = (const float*)d_in[4];
    const float* edge_lin_b = (const float*)d_in[5];
    const float* aW_W = (const float*)d_in[6];
    const float* aW_b = (const float*)d_in[7];
    const float* aA_W = (const float*)d_in[8];
    const float* aA_b = (const float*)d_in[9];
    const float* nmlp_W1 = (const float*)d_in[10];
    const float* nmlp_b1 = (const float*)d_in[11];
    const float* nmlp_W2 = (const float*)d_in[12];
    const float* nmlp_b2 = (const float*)d_in[13];
    const float* nmlp_W3 = (const float*)d_in[14];
    const float* nmlp_b3 = (const float*)d_in[15];
    const float* dmlp_W1 = (const float*)d_in[16];
    const float* dmlp_b1 = (const float*)d_in[17];
    const float* dmlp_W2 = (const float*)d_in[18];
    const float* dmlp_b2 = (const float*)d_in[19];
    const float* emlp_W1 = (const float*)d_in[20];
    const float* emlp_b1 = (const float*)d_in[21];
    const float* emlp_W2 = (const float*)d_in[22];
    const float* emlp_b2 = (const float*)d_in[23];
    const float* emlp_W3 = (const float*)d_in[24];
    const float* emlp_b3 = (const float*)d_in[25];
    const float* aggr_W = (const float*)d_in[26];
    const float* aggr_b = (const float*)d_in[27];
    const float* n1_g = (const float*)d_in[28];
    const float* n1_b = (const float*)d_in[29];
    const float* e_g = (const float*)d_in[30];
    const float* e_b = (const float*)d_in[31];

    float *p_nodes, *p_eattr, *p_nupd, *p_nupd2, *p_scores, *p_agg, *p_upd, *p_hid, *p_dense;
    cudaGetSymbolAddress((void**)&p_nodes, g_nodes);
    cudaGetSymbolAddress((void**)&p_eattr, g_eattr);
    cudaGetSymbolAddress((void**)&p_nupd, g_nupd);
    cudaGetSymbolAddress((void**)&p_nupd2, g_nupd2);
    cudaGetSymbolAddress((void**)&p_scores, g_scores);
    cudaGetSymbolAddress((void**)&p_agg, g_agg);
    cudaGetSymbolAddress((void**)&p_upd, g_upd);
    cudaGetSymbolAddress((void**)&p_hid, g_hid);
    cudaGetSymbolAddress((void**)&p_dense, g_dense);

    // setup
    embed_k<<<(Nn * 128 + 255) / 256, 256>>>(seq, seq_embed);
    rbf_k<<<Ee, 128>>>(dist, edge_lin_W, edge_lin_b);
    zero_cnt_k<<<(Nn + 255) / 256, 256>>>();
    count_k<<<(Ee + 255) / 256, 256>>>(snkI);
    scan_k<<<1, 1024>>>();
    place_k<<<(Ee + 255) / 256, 256>>>(snkI);

    auto gemm = [&](int M, int K, int nBlk, int zDim,
                    const float* A, const float* B, int Nld, long long bSz,
                    const float* bias, int biSz,
                    float* Cp, int ldc, long long cSz,
                    int act, int feat,
                    const float* aAv, const float* aAb) {
        dim3 g(nBlk, (M + 63) / 64, zDim);
        gemm_k<<<g, 256>>>(M, K, A, B, Nld, bSz, bias, biSz, Cp, ldc, cSz,
                           act, feat, p_nodes, p_eattr, srcI, snkI, aAv, aAb);
    };

    for (int l = 0; l < 2; l++) {
        // attention scores: h = lrelu(feat @ aW + b), scores = h . aA + aA_b
        gemm(Ee, Cc, 1, 4, nullptr,
             aW_W + (long long)l * Hh * Cc * Dd, Dd, (long long)Cc * Dd,
             aW_b + l * Hh * Dd, Dd,
             p_scores, 0, 0, 2, 1,
             aA_W + l * Hh * Dd, aA_b + l * Hh);
        // node-message MLP on feat
        gemm(Ee, Cc, 1, 1, nullptr, nmlp_W1 + (long long)l * Cc * Dd, Dd, 0,
             nmlp_b1 + l * Dd, 0, p_nupd, Dd, 0, 1, 1, nullptr, nullptr);
        gemm(Ee, Dd, 1, 1, p_nupd, nmlp_W2 + (long long)l * Dd * Dd, Dd, 0,
             nmlp_b2 + l * Dd, 0, p_nupd2, Dd, 0, 1, 0, nullptr, nullptr);
        gemm(Ee, Dd, 1, 1, p_nupd2, nmlp_W3 + (long long)l * Dd * Dd, Dd, 0,
             nmlp_b3 + l * Dd, 0, p_nupd, Dd, 0, 0, 0, nullptr, nullptr);
        // scatter softmax + weighted aggregation (CSR, deterministic per node)
        agg_k<<<Nn, 128>>>();
        // upd = agg @ aggr_W + b
        gemm(Nn, Hh * Dd, 1, 1, p_agg, aggr_W + (long long)l * Hh * Dd * Dd, Dd, 0,
             aggr_b + l * Dd, 0, p_upd, Dd, 0, 0, 0, nullptr, nullptr);
        // nodes = LN(nodes + upd)
        ln_k<<<Nn, 128>>>(p_nodes, p_upd, n1_g + l * Dd, n1_b + l * Dd, p_nodes);
        // dense MLP
        gemm(Nn, Dd, 4, 1, p_nodes, dmlp_W1 + (long long)l * Dd * 4 * Dd, 4 * Dd, 0,
             dmlp_b1 + l * 4 * Dd, 0, p_hid, 4 * Dd, 0, 1, 0, nullptr, nullptr);
        gemm(Nn, 4 * Dd, 1, 1, p_hid, dmlp_W2 + (long long)l * 4 * Dd * Dd, Dd, 0,
             dmlp_b2 + l * Dd, 0, p_dense, Dd, 0, 0, 0, nullptr, nullptr);
        // nodes = LN(dense + upd)  (residual re-adds attention update, per reference)
        ln_k<<<Nn, 128>>>(p_dense, p_upd, n1_g + l * Dd, n1_b + l * Dd, p_nodes);
        // edge MLP on ef = [nodes_new[src], nodes_new[snk], eattr]
        gemm(Ee, Cc, 1, 1, nullptr, emlp_W1 + (long long)l * Cc * Dd, Dd, 0,
             emlp_b1 + l * Dd, 0, p_nupd, Dd, 0, 1, 1, nullptr, nullptr);
        gemm(Ee, Dd, 1, 1, p_nupd, emlp_W2 + (long long)l * Dd * Dd, Dd, 0,
             emlp_b2 + l * Dd, 0, p_nupd2, Dd, 0, 1, 0, nullptr, nullptr);
        gemm(Ee, Dd, 1, 1, p_nupd2, emlp_W3 + (long long)l * Dd * Dd, Dd, 0,
             emlp_b3 + l * Dd, 0, p_nupd, Dd, 0, 0, 0, nullptr, nullptr);
        // eattr = LN(eattr + eu)
        ln_k<<<Ee, 128>>>(p_eattr, p_nupd, e_g + l * Dd, e_b + l * Dd, p_eattr);
    }

    long long tot = (long long)Nn * 128 + (long long)Ee * 128;
    out_k<<<(int)((tot + 255) / 256), 256>>>((float*)d_out);
}

// round 5
// speedup vs baseline: 1.1022x; 1.1022x over previous
#include <cuda_runtime.h>
#include <cuda_bf16.h>
#include <math.h>
#include <stdint.h>

#define Nn 6000
#define Ee 120000
#define Dd 128
#define Hh 4
#define Cc 384

// ---------------- scratch (device globals; no allocation allowed) ----------------
__device__ __align__(16) float g_nodes[Nn * Dd];
__device__ __align__(16) float g_eattr[Ee * Dd];
__device__ __align__(16) float g_nupd[Ee * Dd];
__device__ __align__(16) float g_nupd2[Ee * Dd];
__device__ __align__(16) float g_scores[Ee * Hh];
__device__ __align__(16) float g_agg[Nn * Hh * Dd];
__device__ __align__(16) float g_upd[Nn * Dd];
__device__ __align__(16) float g_hid[Nn * 4 * Dd];
__device__ __align__(16) float g_dense[Nn * Dd];
__device__ int g_cnt[Nn];
__device__ int g_off[Nn + 1];
__device__ int g_cur[Nn];
__device__ int g_csr[Ee];
// transposed + bf16-split weights: [N, K] row-major per matrix
#define WT_LAYER 557056
__device__ __align__(16) __nv_bfloat16 g_wTh[2 * WT_LAYER];
__device__ __align__(16) __nv_bfloat16 g_wTl[2 * WT_LAYER];

__device__ __forceinline__ float gelu_f(float x) {
    return 0.5f * x * (1.0f + erff(x * 0.70710678118654752f));
}

__device__ __forceinline__ uint32_t smem_u32(const void* p) {
    uint32_t a;
    asm("{ .reg .u64 t; cvta.to.shared.u64 t, %1; cvt.u32.u64 %0, t; }" : "=r"(a) : "l"(p));
    return a;
}
__device__ __forceinline__ void ldsm4(uint32_t* r, uint32_t addr) {
    asm volatile("ldmatrix.sync.aligned.m8n8.x4.shared.b16 {%0,%1,%2,%3}, [%4];"
                 : "=r"(r[0]), "=r"(r[1]), "=r"(r[2]), "=r"(r[3]) : "r"(addr));
}
__device__ __forceinline__ void mma16816(float* d, const uint32_t* a, const uint32_t* b) {
    asm volatile("mma.sync.aligned.m16n8k16.row.col.f32.bf16.bf16.f32 "
                 "{%0,%1,%2,%3}, {%4,%5,%6,%7}, {%8,%9}, {%0,%1,%2,%3};"
                 : "+f"(d[0]), "+f"(d[1]), "+f"(d[2]), "+f"(d[3])
                 : "r"(a[0]), "r"(a[1]), "r"(a[2]), "r"(a[3]), "r"(b[0]), "r"(b[1]));
}

// ---------------- HMMA GEMM: C[M, Ntot] 128x128 tile per CTA ----------------
// act: 0 none, 1 gelu, 2 score (lrelu + dot aA per head z, n0==0)
// featMode: A row m = [nodes[src[m]], nodes[snk[m]], eattr[m]] (K=384)
// hi/lo bf16 split, 3 mma passes: Ah*Bh + Ah*Bl + Al*Bh  (emulated fp32)
#define APAD 40
__global__ void __launch_bounds__(256) gemm_tc(
    int M, int K,
    const float* __restrict__ A,
    const __nv_bfloat16* __restrict__ BTh,
    const __nv_bfloat16* __restrict__ BTl,
    const float* __restrict__ bias,
    float* __restrict__ Cout, int ldc,
    int act, int featMode,
    const float* __restrict__ nodes, const float* __restrict__ eattr,
    const int* __restrict__ srcI, const int* __restrict__ snkI,
    const float* __restrict__ aAv, const float* __restrict__ aAb)
{
    __shared__ __nv_bfloat16 Ah[128][APAD], Al[128][APAD];
    __shared__ __nv_bfloat16 Bh[128][APAD], Bl[128][APAD];
    __shared__ float part[128][2];

    const int tid = threadIdx.x, wid = tid >> 5, lane = tid & 31;
    const int m0 = blockIdx.y * 128, n0 = blockIdx.x * 128, z = blockIdx.z;
    if (act == 2) {
        size_t zo = (size_t)z * K * 128;
        BTh += zo; BTl += zo; bias += z * 128; aAv += z * 128;
    }
    const int mrow0 = (wid & 3) * 32;     // warp: 32 M-rows
    const int ncol0 = (wid >> 2) * 64;    // warp: 64 N-cols
    // ldmatrix lane addressing (same for A and B): 4 8x8 matrices
    const int rowoff = ((lane >> 3) & 1) * 8 + (lane & 7);
    const int coloff = (lane >> 4) * 8;

    float acc[2][8][4];
#pragma unroll
    for (int i = 0; i < 2; i++)
#pragma unroll
        for (int j = 0; j < 8; j++)
#pragma unroll
            for (int q = 0; q < 4; q++) acc[i][j][q] = 0.f;

    const int nCh = K >> 5;
    for (int c = 0; c < nCh; ++c) {
        const int k0 = c << 5;
        // ---- A tile: 128 x 32 fp32 -> bf16 hi/lo ----
#pragma unroll
        for (int it = 0; it < 4; ++it) {
            int idx = tid + it * 256;
            int r = idx >> 3, c4 = (idx & 7) << 2;
            int m = m0 + r;
            float4 v = make_float4(0.f, 0.f, 0.f, 0.f);
            if (m < M) {
                int kg = k0 + c4;
                const float* p;
                if (!featMode) p = A + (size_t)m * K + kg;
                else if (kg < 128) p = nodes + (size_t)srcI[m] * 128 + kg;
                else if (kg < 256) p = nodes + (size_t)snkI[m] * 128 + (kg - 128);
                else p = eattr + (size_t)m * 128 + (kg - 256);
                v = *(const float4*)p;
            }
            __nv_bfloat16 h0 = __float2bfloat16_rn(v.x), h1 = __float2bfloat16_rn(v.y);
            __nv_bfloat16 h2 = __float2bfloat16_rn(v.z), h3 = __float2bfloat16_rn(v.w);
            __nv_bfloat16 l0 = __float2bfloat16_rn(v.x - __bfloat162float(h0));
            __nv_bfloat16 l1 = __float2bfloat16_rn(v.y - __bfloat162float(h1));
            __nv_bfloat16 l2 = __float2bfloat16_rn(v.z - __bfloat162float(h2));
            __nv_bfloat16 l3 = __float2bfloat16_rn(v.w - __bfloat162float(h3));
            uint2 hw = make_uint2(((uint32_t)__bfloat16_as_ushort(h1) << 16) | __bfloat16_as_ushort(h0),
                                  ((uint32_t)__bfloat16_as_ushort(h3) << 16) | __bfloat16_as_ushort(h2));
            uint2 lw = make_uint2(((uint32_t)__bfloat16_as_ushort(l1) << 16) | __bfloat16_as_ushort(l0),
                                  ((uint32_t)__bfloat16_as_ushort(l3) << 16) | __bfloat16_as_ushort(l2));
            *(uint2*)&Ah[r][c4] = hw;
            *(uint2*)&Al[r][c4] = lw;
        }
        // ---- B tile: 128(n) x 32(k), pre-split bf16 ----
#pragma unroll
        for (int it = 0; it < 2; ++it) {
            int idx = tid + it * 256;
            int r = idx >> 2, g = (idx & 3) << 3;
            size_t so = (size_t)(n0 + r) * K + k0 + g;
            *(uint4*)&Bh[r][g] = *(const uint4*)(BTh + so);
            *(uint4*)&Bl[r][g] = *(const uint4*)(BTl + so);
        }
        __syncthreads();
        // ---- compute: 2 k16 steps ----
#pragma unroll
        for (int ks = 0; ks < 2; ++ks) {
            const int kc = ks * 16 + coloff;
            uint32_t ah[2][4], al[2][4];
#pragma unroll
            for (int ma = 0; ma < 2; ++ma) {
                int r = mrow0 + ma * 16 + rowoff;
                ldsm4(ah[ma], smem_u32(&Ah[r][kc]));
                ldsm4(al[ma], smem_u32(&Al[r][kc]));
            }
            uint32_t bh[8][2], bl[8][2];
#pragma unroll
            for (int ng = 0; ng < 4; ++ng) {
                int r = ncol0 + ng * 16 + rowoff;
                uint32_t t[4];
                ldsm4(t, smem_u32(&Bh[r][kc]));
                bh[2 * ng][0] = t[0]; bh[2 * ng][1] = t[2];
                bh[2 * ng + 1][0] = t[1]; bh[2 * ng + 1][1] = t[3];
                ldsm4(t, smem_u32(&Bl[r][kc]));
                bl[2 * ng][0] = t[0]; bl[2 * ng][1] = t[2];
                bl[2 * ng + 1][0] = t[1]; bl[2 * ng + 1][1] = t[3];
            }
#pragma unroll
            for (int ma = 0; ma < 2; ++ma)
#pragma unroll
                for (int na = 0; na < 8; ++na) {
                    mma16816(acc[ma][na], ah[ma], bh[na]);
                    mma16816(acc[ma][na], ah[ma], bl[na]);
                    mma16816(acc[ma][na], al[ma], bh[na]);
                }
        }
        __syncthreads();
    }

    // ---- epilogue ----
    const int qr = lane >> 2, qc = (lane & 3) * 2;
    if (act == 2) {
        const int nh = wid >> 2;   // n-half 0/1
        float s[2][2] = {{0.f, 0.f}, {0.f, 0.f}};   // [ma][row-subgroup]
#pragma unroll
        for (int ma = 0; ma < 2; ++ma)
#pragma unroll
            for (int na = 0; na < 8; ++na) {
                int n = ncol0 + na * 8 + qc;
#pragma unroll
                for (int j = 0; j < 2; ++j) {
                    float v0 = acc[ma][na][j] + bias[n + j];
                    v0 = v0 > 0.f ? v0 : 0.2f * v0;
                    s[ma][0] += v0 * aAv[n + j];
                    float v1 = acc[ma][na][2 + j] + bias[n + j];
                    v1 = v1 > 0.f ? v1 : 0.2f * v1;
                    s[ma][1] += v1 * aAv[n + j];
                }
            }
#pragma unroll
        for (int ma = 0; ma < 2; ++ma)
#pragma unroll
            for (int g = 0; g < 2; ++g) {
                s[ma][g] += __shfl_xor_sync(0xffffffffu, s[ma][g], 1);
                s[ma][g] += __shfl_xor_sync(0xffffffffu, s[ma][g], 2);
            }
        if ((lane & 3) == 0) {
#pragma unroll
            for (int ma = 0; ma < 2; ++ma) {
                part[mrow0 + ma * 16 + qr][nh] = s[ma][0];
                part[mrow0 + ma * 16 + 8 + qr][nh] = s[ma][1];
            }
        }
        __syncthreads();
        if (tid < 128) {
            int m = m0 + tid;
            if (m < M) Cout[(size_t)m * 4 + z] = part[tid][0] + part[tid][1] + aAb[z];
        }
        return;
    }
#pragma unroll
    for (int ma = 0; ma < 2; ++ma) {
        int mA = m0 + mrow0 + ma * 16 + qr;
        int mB = mA + 8;
#pragma unroll
        for (int na = 0; na < 8; ++na) {
            int n = n0 + ncol0 + na * 8 + qc;
            float2 oA, oB;
            oA.x = acc[ma][na][0] + bias[n];
            oA.y = acc[ma][na][1] + bias[n + 1];
            oB.x = acc[ma][na][2] + bias[n];
            oB.y = acc[ma][na][3] + bias[n + 1];
            if (act == 1) {
                oA.x = gelu_f(oA.x); oA.y = gelu_f(oA.y);
                oB.x = gelu_f(oB.x); oB.y = gelu_f(oB.y);
            }
            if (mA < M) *(float2*)(Cout + (size_t)mA * ldc + n) = oA;
            if (mB < M) *(float2*)(Cout + (size_t)mB * ldc + n) = oB;
        }
    }
}

// ---------------- weight transpose + bf16 split ----------------
struct TEnt { const float* src; int dstOff; int K; int N; };
struct TTab { TEnt e[26]; };
__global__ void tsplit_k(TTab tab) {
    TEnt E = tab.e[blockIdx.y];
    int i = blockIdx.x * 256 + threadIdx.x;
    int total = E.K * E.N;
    if (i >= total) return;
    int k = i / E.N, n = i % E.N;
    float x = E.src[i];
    __nv_bfloat16 h = __float2bfloat16_rn(x);
    __nv_bfloat16 lo = __float2bfloat16_rn(x - __bfloat162float(h));
    g_wTh[E.dstOff + (size_t)n * E.K + k] = h;
    g_wTl[E.dstOff + (size_t)n * E.K + k] = lo;
}

// ---------------- setup kernels ----------------
__global__ void embed_k(const int* __restrict__ seq, const float* __restrict__ emb) {
    int i = blockIdx.x * 256 + threadIdx.x;
    if (i < Nn * 128) {
        int nidx = i >> 7, d = i & 127;
        g_nodes[i] = emb[seq[nidx] * 128 + d];
    }
}

__global__ void rbf_k(const float* __restrict__ dist, const float* __restrict__ W,
                      const float* __restrict__ b) {
    __shared__ float r[16];
    int e = blockIdx.x;
    int t = threadIdx.x;
    if (t < 16) {
        float mu = 2.0f + (20.0f / 15.0f) * (float)t;
        float x = (dist[e] - mu) * (1.0f / 1.25f);
        r[t] = expf(-x * x) + 1e-8f;
    }
    __syncthreads();
    float s = b[t];
#pragma unroll
    for (int j = 0; j < 16; j++) s += r[j] * W[j * 128 + t];
    g_eattr[(long long)e * 128 + t] = s;
}

// ---------------- CSR build ----------------
__global__ void zero_cnt_k() {
    int i = blockIdx.x * 256 + threadIdx.x;
    if (i < Nn) g_cnt[i] = 0;
}
__global__ void count_k(const int* __restrict__ snk) {
    int e = blockIdx.x * 256 + threadIdx.x;
    if (e < Ee) atomicAdd(&g_cnt[snk[e]], 1);
}
__global__ void __launch_bounds__(1024) scan_k() {
    __shared__ int s[1024];
    int t = threadIdx.x;
    const int CH = (Nn + 1023) / 1024;
    int st = t * CH;
    int en = st + CH; if (en > Nn) en = Nn; if (st > Nn) st = Nn;
    int loc = 0;
    for (int i = st; i < en; i++) loc += g_cnt[i];
    s[t] = loc;
    __syncthreads();
    for (int d = 1; d < 1024; d <<= 1) {
        int v = (t >= d) ? s[t - d] : 0;
        __syncthreads();
        s[t] += v;
        __syncthreads();
    }
    int run = (t == 0) ? 0 : s[t - 1];
    for (int i = st; i < en; i++) {
        g_off[i] = run; g_cur[i] = run; run += g_cnt[i];
    }
    if (t == 1023) g_off[Nn] = s[1023];
}
__global__ void place_k(const int* __restrict__ snk) {
    int e = blockIdx.x * 256 + threadIdx.x;
    if (e < Ee) {
        int p = atomicAdd(&g_cur[snk[e]], 1);
        g_csr[p] = e;
    }
}

// ---------------- per-node softmax + aggregation ----------------
__global__ void __launch_bounds__(128) agg_k() {
    __shared__ float red[4][128];
    int n = blockIdx.x, t = threadIdx.x;
    int beg = g_off[n], end = g_off[n + 1];
    const float4* sc4 = (const float4*)g_scores;

    float mx[4] = {-1e30f, -1e30f, -1e30f, -1e30f};
    for (int i = beg + t; i < end; i += 128) {
        float4 s = sc4[g_csr[i]];
        mx[0] = fmaxf(mx[0], s.x); mx[1] = fmaxf(mx[1], s.y);
        mx[2] = fmaxf(mx[2], s.z); mx[3] = fmaxf(mx[3], s.w);
    }
#pragma unroll
    for (int h = 0; h < 4; h++) red[h][t] = mx[h];
    __syncthreads();
    for (int s = 64; s > 0; s >>= 1) {
        if (t < s)
#pragma unroll
            for (int h = 0; h < 4; h++) red[h][t] = fmaxf(red[h][t], red[h][t + s]);
        __syncthreads();
    }
    float mxf[4];
#pragma unroll
    for (int h = 0; h < 4; h++) mxf[h] = red[h][0];
    __syncthreads();

    float sm[4] = {0.f, 0.f, 0.f, 0.f};
    for (int i = beg + t; i < end; i += 128) {
        float4 s = sc4[g_csr[i]];
        sm[0] += expf(s.x - mxf[0]) + 1e-12f;
        sm[1] += expf(s.y - mxf[1]) + 1e-12f;
        sm[2] += expf(s.z - mxf[2]) + 1e-12f;
        sm[3] += expf(s.w - mxf[3]) + 1e-12f;
    }
#pragma unroll
    for (int h = 0; h < 4; h++) red[h][t] = sm[h];
    __syncthreads();
    for (int s = 64; s > 0; s >>= 1) {
        if (t < s)
#pragma unroll
            for (int h = 0; h < 4; h++) red[h][t] += red[h][t + s];
        __syncthreads();
    }
    float nrm[4];
#pragma unroll
    for (int h = 0; h < 4; h++) nrm[h] = red[h][0];

    float acc[4] = {0.f, 0.f, 0.f, 0.f};
    for (int i = beg; i < end; i++) {
        int e = g_csr[i];
        float4 s = sc4[e];
        float a0 = expf(s.x - mxf[0]) / nrm[0];
        float a1 = expf(s.y - mxf[1]) / nrm[1];
        float a2 = expf(s.z - mxf[2]) / nrm[2];
        float a3 = expf(s.w - mxf[3]) / nrm[3];
        float v = g_nupd[(long long)e * 128 + t];
        acc[0] += a0 * v; acc[1] += a1 * v; acc[2] += a2 * v; acc[3] += a3 * v;
    }
    long long base = (long long)n * 512;
#pragma unroll
    for (int h = 0; h < 4; h++) g_agg[base + h * 128 + t] = acc[h];
}

// ---------------- LayerNorm: out = LN(a + r) * g + b ----------------
__global__ void __launch_bounds__(128) ln_k(const float* __restrict__ a,
                                            const float* __restrict__ r,
                                            const float* __restrict__ g,
                                            const float* __restrict__ b,
                                            float* __restrict__ out) {
    int row = blockIdx.x, t = threadIdx.x;
    __shared__ float sh[8];
    long long base = (long long)row * 128;
    float x = a[base + t] + r[base + t];
    float s = x;
#pragma unroll
    for (int o = 16; o; o >>= 1) s += __shfl_xor_sync(0xffffffffu, s, o);
    if ((t & 31) == 0) sh[t >> 5] = s;
    __syncthreads();
    float mean = (sh[0] + sh[1] + sh[2] + sh[3]) * (1.0f / 128.0f);
    float d = x - mean;
    float v = d * d;
#pragma unroll
    for (int o = 16; o; o >>= 1) v += __shfl_xor_sync(0xffffffffu, v, o);
    if ((t & 31) == 0) sh[4 + (t >> 5)] = v;
    __syncthreads();
    float var = (sh[4] + sh[5] + sh[6] + sh[7]) * (1.0f / 128.0f);
    out[base + t] = d * rsqrtf(var + 1e-5f) * g[t] + b[t];
}

// ---------------- copy out ----------------
__global__ void out_k(float* __restrict__ out) {
    long long i = (long long)blockIdx.x * 256 + threadIdx.x;
    const long long nTot = (long long)Nn * 128;
    const long long tot = nTot + (long long)Ee * 128;
    if (i < nTot) out[i] = g_nodes[i];
    else if (i < tot) out[i] = g_eattr[i - nTot];
}

// ---------------- host ----------------
extern "C" void kernel_launch(void* const* d_in, const int* in_sizes, int n_in,
                              void* d_out, int out_size) {
    const int* seq = (const int*)d_in[0];
    const int* eidx = (const int*)d_in[1];
    const int* srcI = eidx;
    const int* snkI = eidx + Ee;
    const float* dist = (const float*)d_in[2];
    const float* seq_embed = (const float*)d_in[3];
    const float* edge_lin_W = (const float*)d_in[4];
    const float* edge_lin_b = (const float*)d_in[5];
    const float* aW_W = (const float*)d_in[6];
    const float* aW_b = (const float*)d_in[7];
    const float* aA_W = (const float*)d_in[8];
    const float* aA_b = (const float*)d_in[9];
    const float* nmlp_W1 = (const float*)d_in[10];
    const float* nmlp_b1 = (const float*)d_in[11];
    const float* nmlp_W2 = (const float*)d_in[12];
    const float* nmlp_b2 = (const float*)d_in[13];
    const float* nmlp_W3 = (const float*)d_in[14];
    const float* nmlp_b3 = (const float*)d_in[15];
    const float* dmlp_W1 = (const float*)d_in[16];
    const float* dmlp_b1 = (const float*)d_in[17];
    const float* dmlp_W2 = (const float*)d_in[18];
    const float* dmlp_b2 = (const float*)d_in[19];
    const float* emlp_W1 = (const float*)d_in[20];
    const float* emlp_b1 = (const float*)d_in[21];
    const float* emlp_W2 = (const float*)d_in[22];
    const float* emlp_b2 = (const float*)d_in[23];
    const float* emlp_W3 = (const float*)d_in[24];
    const float* emlp_b3 = (const float*)d_in[25];
    const float* aggr_W = (const float*)d_in[26];
    const float* aggr_b = (const float*)d_in[27];
    const float* n1_g = (const float*)d_in[28];
    const float* n1_b = (const float*)d_in[29];
    const float* e_g = (const float*)d_in[30];
    const float* e_b = (const float*)d_in[31];

    float *p_nodes, *p_eattr, *p_nupd, *p_nupd2, *p_scores, *p_agg, *p_upd, *p_hid, *p_dense;
    __nv_bfloat16 *pWh, *pWl;
    cudaGetSymbolAddress((void**)&p_nodes, g_nodes);
    cudaGetSymbolAddress((void**)&p_eattr, g_eattr);
    cudaGetSymbolAddress((void**)&p_nupd, g_nupd);
    cudaGetSymbolAddress((void**)&p_nupd2, g_nupd2);
    cudaGetSymbolAddress((void**)&p_scores, g_scores);
    cudaGetSymbolAddress((void**)&p_agg, g_agg);
    cudaGetSymbolAddress((void**)&p_upd, g_upd);
    cudaGetSymbolAddress((void**)&p_hid, g_hid);
    cudaGetSymbolAddress((void**)&p_dense, g_dense);
    cudaGetSymbolAddress((void**)&pWh, g_wTh);
    cudaGetSymbolAddress((void**)&pWl, g_wTl);

    // weight transpose + split (26 matrices)
    TTab tab;
    {
        int idx = 0;
        for (int l = 0; l < 2; l++) {
            int lb = l * WT_LAYER;
            for (int h = 0; h < 4; h++)
                tab.e[idx++] = { aW_W + (size_t)(l * 4 + h) * 384 * 128, lb + h * 49152, 384, 128 };
            tab.e[idx++] = { nmlp_W1 + (size_t)l * 384 * 128, lb + 196608, 384, 128 };
            tab.e[idx++] = { nmlp_W2 + (size_t)l * 128 * 128, lb + 245760, 128, 128 };
            tab.e[idx++] = { nmlp_W3 + (size_t)l * 128 * 128, lb + 262144, 128, 128 };
            tab.e[idx++] = { aggr_W + (size_t)l * 512 * 128, lb + 278528, 512, 128 };
            tab.e[idx++] = { dmlp_W1 + (size_t)l * 128 * 512, lb + 344064, 128, 512 };
            tab.e[idx++] = { dmlp_W2 + (size_t)l * 512 * 128, lb + 409600, 512, 128 };
            tab.e[idx++] = { emlp_W1 + (size_t)l * 384 * 128, lb + 475136, 384, 128 };
            tab.e[idx++] = { emlp_W2 + (size_t)l * 128 * 128, lb + 524288, 128, 128 };
            tab.e[idx++] = { emlp_W3 + (size_t)l * 128 * 128, lb + 540672, 128, 128 };
        }
    }
    tsplit_k<<<dim3(256, 26), 256>>>(tab);

    // setup
    embed_k<<<(Nn * 128 + 255) / 256, 256>>>(seq, seq_embed);
    rbf_k<<<Ee, 128>>>(dist, edge_lin_W, edge_lin_b);
    zero_cnt_k<<<(Nn + 255) / 256, 256>>>();
    count_k<<<(Ee + 255) / 256, 256>>>(snkI);
    scan_k<<<1, 1024>>>();
    place_k<<<(Ee + 255) / 256, 256>>>(snkI);

    auto gemm = [&](int M, int K, int nTile, int zDim, const float* A, long long wOff,
                    const float* bias, float* Cp, int ldc, int act, int feat,
                    const float* aAv, const float* aAb) {
        dim3 g(nTile, (M + 127) / 128, zDim);
        gemm_tc<<<g, 256>>>(M, K, A, pWh + wOff, pWl + wOff, bias, Cp, ldc,
                            act, feat, p_nodes, p_eattr, srcI, snkI, aAv, aAb);
    };

    for (int l = 0; l < 2; l++) {
        long long lb = (long long)l * WT_LAYER;
        // attention scores
        gemm(Ee, Cc, 1, 4, nullptr, lb + 0, aW_b + l * 512, p_scores, 0, 2, 1,
             aA_W + l * 512, aA_b + l * 4);
        // node-message MLP
        gemm(Ee, Cc, 1, 1, nullptr, lb + 196608, nmlp_b1 + l * 128, p_nupd, 128, 1, 1, nullptr, nullptr);
        gemm(Ee, 128, 1, 1, p_nupd, lb + 245760, nmlp_b2 + l * 128, p_nupd2, 128, 1, 0, nullptr, nullptr);
        gemm(Ee, 128, 1, 1, p_nupd2, lb + 262144, nmlp_b3 + l * 128, p_nupd, 128, 0, 0, nullptr, nullptr);
        // scatter softmax + aggregation
        agg_k<<<Nn, 128>>>();
        // upd = agg @ aggr_W + b
        gemm(Nn, 512, 1, 1, p_agg, lb + 278528, aggr_b + l * 128, p_upd, 128, 0, 0, nullptr, nullptr);
        ln_k<<<Nn, 128>>>(p_nodes, p_upd, n1_g + l * 128, n1_b + l * 128, p_nodes);
        // dense MLP
        gemm(Nn, 128, 4, 1, p_nodes, lb + 344064, dmlp_b1 + l * 512, p_hid, 512, 1, 0, nullptr, nullptr);
        gemm(Nn, 512, 1, 1, p_hid, lb + 409600, dmlp_b2 + l * 128, p_dense, 128, 0, 0, nullptr, nullptr);
        ln_k<<<Nn, 128>>>(p_dense, p_upd, n1_g + l * 128, n1_b + l * 128, p_nodes);
        // edge MLP
        gemm(Ee, Cc, 1, 1, nullptr, lb + 475136, emlp_b1 + l * 128, p_nupd, 128, 1, 1, nullptr, nullptr);
        gemm(Ee, 128, 1, 1, p_nupd, lb + 524288, emlp_b2 + l * 128, p_nupd2, 128, 1, 0, nullptr, nullptr);
        gemm(Ee, 128, 1, 1, p_nupd2, lb + 540672, emlp_b3 + l * 128, p_nupd, 128, 0, 0, nullptr, nullptr);
        ln_k<<<Ee, 128>>>(p_eattr, p_nupd, e_g + l * 128, e_b + l * 128, p_eattr);
    }

    long long tot = (long long)Nn * 128 + (long long)Ee * 128;
    out_k<<<(int)((tot + 255) / 256), 256>>>((float*)d_out);
}

// round 6
// speedup vs baseline: 1.3161x; 1.1941x over previous
#include <cuda_runtime.h>
#include <cuda_bf16.h>
#include <math.h>
#include <stdint.h>

#define Nn 6000
#define Ee 120000
#define Dd 128
#define Hh 4
#define Cc 384

// ---------------- scratch (device globals) ----------------
__device__ __align__(16) float g_nodes[Nn * Dd];
__device__ __align__(16) float g_eattr[Ee * Dd];
__device__ __align__(16) float g_nupd[Ee * Dd];
__device__ __align__(16) float g_scores[Ee * Hh];
__device__ __align__(16) float g_upd[Nn * Dd];
__device__ __align__(16) float g_dense[Nn * Dd];
// bf16 hi/lo split activations
__device__ __align__(16) __nv_bfloat16 g_nodesH[Nn * Dd], g_nodesL[Nn * Dd];
__device__ __align__(16) __nv_bfloat16 g_eatH[Ee * Dd], g_eatL[Ee * Dd];
__device__ __align__(16) __nv_bfloat16 g_b1H[Ee * Dd], g_b1L[Ee * Dd];
__device__ __align__(16) __nv_bfloat16 g_b2H[Ee * Dd], g_b2L[Ee * Dd];
__device__ __align__(16) __nv_bfloat16 g_aggH[Nn * 4 * Dd], g_aggL[Nn * 4 * Dd];
__device__ int g_cnt[Nn];
__device__ int g_off[Nn + 1];
__device__ int g_cur[Nn];
__device__ int g_csr[Ee];
// transposed + bf16-split weights: [N, K] row-major per matrix
#define WT_LAYER 557056
__device__ __align__(16) __nv_bfloat16 g_wTh[2 * WT_LAYER];
__device__ __align__(16) __nv_bfloat16 g_wTl[2 * WT_LAYER];

__device__ __forceinline__ float gelu_f(float x) {
    return 0.5f * x * (1.0f + erff(x * 0.70710678118654752f));
}
__device__ __forceinline__ uint32_t smem_u32(const void* p) {
    uint32_t a;
    asm("{ .reg .u64 t; cvta.to.shared.u64 t, %1; cvt.u32.u64 %0, t; }" : "=r"(a) : "l"(p));
    return a;
}
__device__ __forceinline__ void ldsm4(uint32_t* r, uint32_t addr) {
    asm volatile("ldmatrix.sync.aligned.m8n8.x4.shared.b16 {%0,%1,%2,%3}, [%4];"
                 : "=r"(r[0]), "=r"(r[1]), "=r"(r[2]), "=r"(r[3]) : "r"(addr));
}
__device__ __forceinline__ void mma16816(float* d, const uint32_t* a, const uint32_t* b) {
    asm volatile("mma.sync.aligned.m16n8k16.row.col.f32.bf16.bf16.f32 "
                 "{%0,%1,%2,%3}, {%4,%5,%6,%7}, {%8,%9}, {%0,%1,%2,%3};"
                 : "+f"(d[0]), "+f"(d[1]), "+f"(d[2]), "+f"(d[3])
                 : "r"(a[0]), "r"(a[1]), "r"(a[2]), "r"(a[3]), "r"(b[0]), "r"(b[1]));
}
__device__ __forceinline__ void split2(float x, __nv_bfloat16& h, __nv_bfloat16& l) {
    h = __float2bfloat16_rn(x);
    l = __float2bfloat16_rn(x - __bfloat162float(h));
}

// ---------------- HMMA GEMM: 128x128 tile per CTA, pre-split bf16 A/B ----------------
// act: 0 none, 1 gelu, 2 score (lrelu + dot aA per head z, n0==0)
// featMode: A row m = [nodes[src[m]], nodes[snk[m]], eattr[m]] (K=384)
// outSplit: write bf16 hi/lo pair instead of fp32
#define APAD 40
__global__ void __launch_bounds__(256) gemm_tc(
    int M, int K,
    const __nv_bfloat16* __restrict__ AhG, const __nv_bfloat16* __restrict__ AlG,
    const __nv_bfloat16* __restrict__ BTh, const __nv_bfloat16* __restrict__ BTl,
    const float* __restrict__ bias,
    float* __restrict__ Cout,
    __nv_bfloat16* __restrict__ CoH, __nv_bfloat16* __restrict__ CoL, int ldc,
    int act, int featMode, int outSplit,
    const __nv_bfloat16* __restrict__ ndH, const __nv_bfloat16* __restrict__ ndL,
    const __nv_bfloat16* __restrict__ eaH, const __nv_bfloat16* __restrict__ eaL,
    const int* __restrict__ srcI, const int* __restrict__ snkI,
    const float* __restrict__ aAv, const float* __restrict__ aAb)
{
    __shared__ __nv_bfloat16 Ah[128][APAD], Al[128][APAD];
    __shared__ __nv_bfloat16 Bh[128][APAD], Bl[128][APAD];
    __shared__ float part[128][2];

    const int tid = threadIdx.x, wid = tid >> 5, lane = tid & 31;
    const int m0 = blockIdx.y * 128, n0 = blockIdx.x * 128, z = blockIdx.z;
    if (act == 2) {
        size_t zo = (size_t)z * K * 128;
        BTh += zo; BTl += zo; bias += z * 128; aAv += z * 128;
    }
    const int mrow0 = (wid & 3) * 32;
    const int ncol0 = (wid >> 2) * 64;
    const int rowoff = ((lane >> 3) & 1) * 8 + (lane & 7);
    const int coloff = (lane >> 4) * 8;

    float acc[2][8][4];
#pragma unroll
    for (int i = 0; i < 2; i++)
#pragma unroll
        for (int j = 0; j < 8; j++)
#pragma unroll
            for (int q = 0; q < 4; q++) acc[i][j][q] = 0.f;

    const int nCh = K >> 5;
    for (int c = 0; c < nCh; ++c) {
        const int k0 = c << 5;
        // ---- A tile: 128 rows x 32 k bf16 (pre-split), uint4 = 8 bf16 ----
#pragma unroll
        for (int it = 0; it < 2; ++it) {
            int idx = tid + it * 256;          // 512 groups: 128 rows x 4 k-groups
            int r = idx >> 2, g = (idx & 3) << 3;
            int mm = m0 + r; if (mm >= M) mm = M - 1;
            int kg = k0 + g;
            const __nv_bfloat16 *ph, *pl;
            if (!featMode) { ph = AhG + (size_t)mm * K + kg; pl = AlG + (size_t)mm * K + kg; }
            else if (kg < 128) { int s = srcI[mm]; ph = ndH + (size_t)s * 128 + kg; pl = ndL + (size_t)s * 128 + kg; }
            else if (kg < 256) { int s = snkI[mm]; ph = ndH + (size_t)s * 128 + (kg - 128); pl = ndL + (size_t)s * 128 + (kg - 128); }
            else { ph = eaH + (size_t)mm * 128 + (kg - 256); pl = eaL + (size_t)mm * 128 + (kg - 256); }
            *(uint4*)&Ah[r][g] = *(const uint4*)ph;
            *(uint4*)&Al[r][g] = *(const uint4*)pl;
        }
        // ---- B tile: 128(n) x 32(k) ----
#pragma unroll
        for (int it = 0; it < 2; ++it) {
            int idx = tid + it * 256;
            int r = idx >> 2, g = (idx & 3) << 3;
            size_t so = (size_t)(n0 + r) * K + k0 + g;
            *(uint4*)&Bh[r][g] = *(const uint4*)(BTh + so);
            *(uint4*)&Bl[r][g] = *(const uint4*)(BTl + so);
        }
        __syncthreads();
#pragma unroll
        for (int ks = 0; ks < 2; ++ks) {
            const int kc = ks * 16 + coloff;
            uint32_t ah[2][4], al[2][4];
#pragma unroll
            for (int ma = 0; ma < 2; ++ma) {
                int r = mrow0 + ma * 16 + rowoff;
                ldsm4(ah[ma], smem_u32(&Ah[r][kc]));
                ldsm4(al[ma], smem_u32(&Al[r][kc]));
            }
            uint32_t bh[8][2], bl[8][2];
#pragma unroll
            for (int ng = 0; ng < 4; ++ng) {
                int r = ncol0 + ng * 16 + rowoff;
                uint32_t t[4];
                ldsm4(t, smem_u32(&Bh[r][kc]));
                bh[2 * ng][0] = t[0]; bh[2 * ng][1] = t[2];
                bh[2 * ng + 1][0] = t[1]; bh[2 * ng + 1][1] = t[3];
                ldsm4(t, smem_u32(&Bl[r][kc]));
                bl[2 * ng][0] = t[0]; bl[2 * ng][1] = t[2];
                bl[2 * ng + 1][0] = t[1]; bl[2 * ng + 1][1] = t[3];
            }
            // pass-major: 16 independent MMAs per pass -> acc reuse distance 16
#pragma unroll
            for (int ma = 0; ma < 2; ++ma)
#pragma unroll
                for (int na = 0; na < 8; ++na) mma16816(acc[ma][na], ah[ma], bh[na]);
#pragma unroll
            for (int ma = 0; ma < 2; ++ma)
#pragma unroll
                for (int na = 0; na < 8; ++na) mma16816(acc[ma][na], ah[ma], bl[na]);
#pragma unroll
            for (int ma = 0; ma < 2; ++ma)
#pragma unroll
                for (int na = 0; na < 8; ++na) mma16816(acc[ma][na], al[ma], bh[na]);
        }
        __syncthreads();
    }

    // ---- epilogue ----
    const int qr = lane >> 2, qc = (lane & 3) * 2;
    if (act == 2) {
        const int nh = wid >> 2;
        float s[2][2] = {{0.f, 0.f}, {0.f, 0.f}};
#pragma unroll
        for (int ma = 0; ma < 2; ++ma)
#pragma unroll
            for (int na = 0; na < 8; ++na) {
                int n = ncol0 + na * 8 + qc;
#pragma unroll
                for (int j = 0; j < 2; ++j) {
                    float v0 = acc[ma][na][j] + bias[n + j];
                    v0 = v0 > 0.f ? v0 : 0.2f * v0;
                    s[ma][0] += v0 * aAv[n + j];
                    float v1 = acc[ma][na][2 + j] + bias[n + j];
                    v1 = v1 > 0.f ? v1 : 0.2f * v1;
                    s[ma][1] += v1 * aAv[n + j];
                }
            }
#pragma unroll
        for (int ma = 0; ma < 2; ++ma)
#pragma unroll
            for (int g = 0; g < 2; ++g) {
                s[ma][g] += __shfl_xor_sync(0xffffffffu, s[ma][g], 1);
                s[ma][g] += __shfl_xor_sync(0xffffffffu, s[ma][g], 2);
            }
        if ((lane & 3) == 0) {
#pragma unroll
            for (int ma = 0; ma < 2; ++ma) {
                part[mrow0 + ma * 16 + qr][nh] = s[ma][0];
                part[mrow0 + ma * 16 + 8 + qr][nh] = s[ma][1];
            }
        }
        __syncthreads();
        if (tid < 128) {
            int m = m0 + tid;
            if (m < M) Cout[(size_t)m * 4 + z] = part[tid][0] + part[tid][1] + aAb[z];
        }
        return;
    }
#pragma unroll
    for (int ma = 0; ma < 2; ++ma) {
        int mA = m0 + mrow0 + ma * 16 + qr;
        int mB = mA + 8;
#pragma unroll
        for (int na = 0; na < 8; ++na) {
            int n = n0 + ncol0 + na * 8 + qc;
            float2 oA, oB;
            oA.x = acc[ma][na][0] + bias[n];
            oA.y = acc[ma][na][1] + bias[n + 1];
            oB.x = acc[ma][na][2] + bias[n];
            oB.y = acc[ma][na][3] + bias[n + 1];
            if (act == 1) {
                oA.x = gelu_f(oA.x); oA.y = gelu_f(oA.y);
                oB.x = gelu_f(oB.x); oB.y = gelu_f(oB.y);
            }
            if (outSplit) {
                __nv_bfloat16 h0, l0, h1, l1;
                if (mA < M) {
                    split2(oA.x, h0, l0); split2(oA.y, h1, l1);
                    *(uint32_t*)(CoH + (size_t)mA * ldc + n) =
                        ((uint32_t)__bfloat16_as_ushort(h1) << 16) | __bfloat16_as_ushort(h0);
                    *(uint32_t*)(CoL + (size_t)mA * ldc + n) =
                        ((uint32_t)__bfloat16_as_ushort(l1) << 16) | __bfloat16_as_ushort(l0);
                }
                if (mB < M) {
                    split2(oB.x, h0, l0); split2(oB.y, h1, l1);
                    *(uint32_t*)(CoH + (size_t)mB * ldc + n) =
                        ((uint32_t)__bfloat16_as_ushort(h1) << 16) | __bfloat16_as_ushort(h0);
                    *(uint32_t*)(CoL + (size_t)mB * ldc + n) =
                        ((uint32_t)__bfloat16_as_ushort(l1) << 16) | __bfloat16_as_ushort(l0);
                }
            } else {
                if (mA < M) *(float2*)(Cout + (size_t)mA * ldc + n) = oA;
                if (mB < M) *(float2*)(Cout + (size_t)mB * ldc + n) = oB;
            }
        }
    }
}

// ---------------- weight transpose + bf16 split ----------------
struct TEnt { const float* src; int dstOff; int K; int N; };
struct TTab { TEnt e[26]; };
__global__ void tsplit_k(TTab tab) {
    TEnt E = tab.e[blockIdx.y];
    int i = blockIdx.x * 256 + threadIdx.x;
    int total = E.K * E.N;
    if (i >= total) return;
    int k = i / E.N, n = i % E.N;
    float x = E.src[i];
    __nv_bfloat16 h, l;
    split2(x, h, l);
    g_wTh[E.dstOff + (size_t)n * E.K + k] = h;
    g_wTl[E.dstOff + (size_t)n * E.K + k] = l;
}

// ---------------- activation split ----------------
__global__ void split_k(const float* __restrict__ src, __nv_bfloat16* __restrict__ h,
                        __nv_bfloat16* __restrict__ l, int count) {
    int i = blockIdx.x * 256 + threadIdx.x;
    if (i < count) {
        __nv_bfloat16 hh, ll;
        split2(src[i], hh, ll);
        h[i] = hh; l[i] = ll;
    }
}

// ---------------- setup ----------------
__global__ void embed_k(const int* __restrict__ seq, const float* __restrict__ emb) {
    int i = blockIdx.x * 256 + threadIdx.x;
    if (i < Nn * 128) {
        int nidx = i >> 7, d = i & 127;
        g_nodes[i] = emb[seq[nidx] * 128 + d];
    }
}
__global__ void rbf_k(const float* __restrict__ dist, const float* __restrict__ W,
                      const float* __restrict__ b) {
    __shared__ float r[16];
    int e = blockIdx.x;
    int t = threadIdx.x;
    if (t < 16) {
        float mu = 2.0f + (20.0f / 15.0f) * (float)t;
        float x = (dist[e] - mu) * (1.0f / 1.25f);
        r[t] = expf(-x * x) + 1e-8f;
    }
    __syncthreads();
    float s = b[t];
#pragma unroll
    for (int j = 0; j < 16; j++) s += r[j] * W[j * 128 + t];
    g_eattr[(long long)e * 128 + t] = s;
}

// ---------------- CSR ----------------
__global__ void zero_cnt_k() {
    int i = blockIdx.x * 256 + threadIdx.x;
    if (i < Nn) g_cnt[i] = 0;
}
__global__ void count_k(const int* __restrict__ snk) {
    int e = blockIdx.x * 256 + threadIdx.x;
    if (e < Ee) atomicAdd(&g_cnt[snk[e]], 1);
}
__global__ void __launch_bounds__(1024) scan_k() {
    __shared__ int s[1024];
    int t = threadIdx.x;
    const int CH = (Nn + 1023) / 1024;
    int st = t * CH;
    int en = st + CH; if (en > Nn) en = Nn; if (st > Nn) st = Nn;
    int loc = 0;
    for (int i = st; i < en; i++) loc += g_cnt[i];
    s[t] = loc;
    __syncthreads();
    for (int d = 1; d < 1024; d <<= 1) {
        int v = (t >= d) ? s[t - d] : 0;
        __syncthreads();
        s[t] += v;
        __syncthreads();
    }
    int run = (t == 0) ? 0 : s[t - 1];
    for (int i = st; i < en; i++) {
        g_off[i] = run; g_cur[i] = run; run += g_cnt[i];
    }
    if (t == 1023) g_off[Nn] = s[1023];
}
__global__ void place_k(const int* __restrict__ snk) {
    int e = blockIdx.x * 256 + threadIdx.x;
    if (e < Ee) {
        int p = atomicAdd(&g_cur[snk[e]], 1);
        g_csr[p] = e;
    }
}

// ---------------- per-node softmax + aggregation (writes split bf16) ----------------
__global__ void __launch_bounds__(128) agg_k() {
    __shared__ float red[4][128];
    int n = blockIdx.x, t = threadIdx.x;
    int beg = g_off[n], end = g_off[n + 1];
    const float4* sc4 = (const float4*)g_scores;

    float mx[4] = {-1e30f, -1e30f, -1e30f, -1e30f};
    for (int i = beg + t; i < end; i += 128) {
        float4 s = sc4[g_csr[i]];
        mx[0] = fmaxf(mx[0], s.x); mx[1] = fmaxf(mx[1], s.y);
        mx[2] = fmaxf(mx[2], s.z); mx[3] = fmaxf(mx[3], s.w);
    }
#pragma unroll
    for (int h = 0; h < 4; h++) red[h][t] = mx[h];
    __syncthreads();
    for (int s = 64; s > 0; s >>= 1) {
        if (t < s)
#pragma unroll
            for (int h = 0; h < 4; h++) red[h][t] = fmaxf(red[h][t], red[h][t + s]);
        __syncthreads();
    }
    float mxf[4];
#pragma unroll
    for (int h = 0; h < 4; h++) mxf[h] = red[h][0];
    __syncthreads();

    float sm[4] = {0.f, 0.f, 0.f, 0.f};
    for (int i = beg + t; i < end; i += 128) {
        float4 s = sc4[g_csr[i]];
        sm[0] += expf(s.x - mxf[0]) + 1e-12f;
        sm[1] += expf(s.y - mxf[1]) + 1e-12f;
        sm[2] += expf(s.z - mxf[2]) + 1e-12f;
        sm[3] += expf(s.w - mxf[3]) + 1e-12f;
    }
#pragma unroll
    for (int h = 0; h < 4; h++) red[h][t] = sm[h];
    __syncthreads();
    for (int s = 64; s > 0; s >>= 1) {
        if (t < s)
#pragma unroll
            for (int h = 0; h < 4; h++) red[h][t] += red[h][t + s];
        __syncthreads();
    }
    float nrm[4];
#pragma unroll
    for (int h = 0; h < 4; h++) nrm[h] = red[h][0];

    float acc[4] = {0.f, 0.f, 0.f, 0.f};
    for (int i = beg; i < end; i++) {
        int e = g_csr[i];
        float4 s = sc4[e];
        float a0 = expf(s.x - mxf[0]) / nrm[0];
        float a1 = expf(s.y - mxf[1]) / nrm[1];
        float a2 = expf(s.z - mxf[2]) / nrm[2];
        float a3 = expf(s.w - mxf[3]) / nrm[3];
        float v = g_nupd[(long long)e * 128 + t];
        acc[0] += a0 * v; acc[1] += a1 * v; acc[2] += a2 * v; acc[3] += a3 * v;
    }
    long long base = (long long)n * 512;
#pragma unroll
    for (int h = 0; h < 4; h++) {
        __nv_bfloat16 hh, ll;
        split2(acc[h], hh, ll);
        g_aggH[base + h * 128 + t] = hh;
        g_aggL[base + h * 128 + t] = ll;
    }
}

// ---------------- LayerNorm ----------------
__global__ void __launch_bounds__(128) ln_k(const float* __restrict__ a,
                                            const float* __restrict__ r,
                                            const float* __restrict__ g,
                                            const float* __restrict__ b,
                                            float* __restrict__ out) {
    int row = blockIdx.x, t = threadIdx.x;
    __shared__ float sh[8];
    long long base = (long long)row * 128;
    float x = a[base + t] + r[base + t];
    float s = x;
#pragma unroll
    for (int o = 16; o; o >>= 1) s += __shfl_xor_sync(0xffffffffu, s, o);
    if ((t & 31) == 0) sh[t >> 5] = s;
    __syncthreads();
    float mean = (sh[0] + sh[1] + sh[2] + sh[3]) * (1.0f / 128.0f);
    float d = x - mean;
    float v = d * d;
#pragma unroll
    for (int o = 16; o; o >>= 1) v += __shfl_xor_sync(0xffffffffu, v, o);
    if ((t & 31) == 0) sh[4 + (t >> 5)] = v;
    __syncthreads();
    float var = (sh[4] + sh[5] + sh[6] + sh[7]) * (1.0f / 128.0f);
    out[base + t] = d * rsqrtf(var + 1e-5f) * g[t] + b[t];
}

// ---------------- copy out ----------------
__global__ void out_k(float* __restrict__ out) {
    long long i = (long long)blockIdx.x * 256 + threadIdx.x;
    const long long nTot = (long long)Nn * 128;
    const long long tot = nTot + (long long)Ee * 128;
    if (i < nTot) out[i] = g_nodes[i];
    else if (i < tot) out[i] = g_eattr[i - nTot];
}

// ---------------- host ----------------
extern "C" void kernel_launch(void* const* d_in, const int* in_sizes, int n_in,
                              void* d_out, int out_size) {
    const int* seq = (const int*)d_in[0];
    const int* eidx = (const int*)d_in[1];
    const int* srcI = eidx;
    const int* snkI = eidx + Ee;
    const float* dist = (const float*)d_in[2];
    const float* seq_embed = (const float*)d_in[3];
    const float* edge_lin_W = (const float*)d_in[4];
    const float* edge_lin_b = (const float*)d_in[5];
    const float* aW_W = (const float*)d_in[6];
    const float* aW_b = (const float*)d_in[7];
    const float* aA_W = (const float*)d_in[8];
    const float* aA_b = (const float*)d_in[9];
    const float* nmlp_W1 = (const float*)d_in[10];
    const float* nmlp_b1 = (const float*)d_in[11];
    const float* nmlp_W2 = (const float*)d_in[12];
    const float* nmlp_b2 = (const float*)d_in[13];
    const float* nmlp_W3 = (const float*)d_in[14];
    const float* nmlp_b3 = (const float*)d_in[15];
    const float* dmlp_W1 = (const float*)d_in[16];
    const float* dmlp_b1 = (const float*)d_in[17];
    const float* dmlp_W2 = (const float*)d_in[18];
    const float* dmlp_b2 = (const float*)d_in[19];
    const float* emlp_W1 = (const float*)d_in[20];
    const float* emlp_b1 = (const float*)d_in[21];
    const float* emlp_W2 = (const float*)d_in[22];
    const float* emlp_b2 = (const float*)d_in[23];
    const float* emlp_W3 = (const float*)d_in[24];
    const float* emlp_b3 = (const float*)d_in[25];
    const float* aggr_W = (const float*)d_in[26];
    const float* aggr_b = (const float*)d_in[27];
    const float* n1_g = (const float*)d_in[28];
    const float* n1_b = (const float*)d_in[29];
    const float* e_g = (const float*)d_in[30];
    const float* e_b = (const float*)d_in[31];

    float *p_nodes, *p_eattr, *p_nupd, *p_scores, *p_upd, *p_dense;
    __nv_bfloat16 *pWh, *pWl, *pNh, *pNl, *pEh, *pEl, *pB1h, *pB1l, *pB2h, *pB2l, *pAgh, *pAgl;
    cudaGetSymbolAddress((void**)&p_nodes, g_nodes);
    cudaGetSymbolAddress((void**)&p_eattr, g_eattr);
    cudaGetSymbolAddress((void**)&p_nupd, g_nupd);
    cudaGetSymbolAddress((void**)&p_scores, g_scores);
    cudaGetSymbolAddress((void**)&p_upd, g_upd);
    cudaGetSymbolAddress((void**)&p_dense, g_dense);
    cudaGetSymbolAddress((void**)&pWh, g_wTh);
    cudaGetSymbolAddress((void**)&pWl, g_wTl);
    cudaGetSymbolAddress((void**)&pNh, g_nodesH);
    cudaGetSymbolAddress((void**)&pNl, g_nodesL);
    cudaGetSymbolAddress((void**)&pEh, g_eatH);
    cudaGetSymbolAddress((void**)&pEl, g_eatL);
    cudaGetSymbolAddress((void**)&pB1h, g_b1H);
    cudaGetSymbolAddress((void**)&pB1l, g_b1L);
    cudaGetSymbolAddress((void**)&pB2h, g_b2H);
    cudaGetSymbolAddress((void**)&pB2l, g_b2L);
    cudaGetSymbolAddress((void**)&pAgh, g_aggH);
    cudaGetSymbolAddress((void**)&pAgl, g_aggL);

    // weight transpose + split (26 matrices)
    TTab tab;
    {
        int idx = 0;
        for (int l = 0; l < 2; l++) {
            int lb = l * WT_LAYER;
            for (int h = 0; h < 4; h++)
                tab.e[idx++] = { aW_W + (size_t)(l * 4 + h) * 384 * 128, lb + h * 49152, 384, 128 };
            tab.e[idx++] = { nmlp_W1 + (size_t)l * 384 * 128, lb + 196608, 384, 128 };
            tab.e[idx++] = { nmlp_W2 + (size_t)l * 128 * 128, lb + 245760, 128, 128 };
            tab.e[idx++] = { nmlp_W3 + (size_t)l * 128 * 128, lb + 262144, 128, 128 };
            tab.e[idx++] = { aggr_W + (size_t)l * 512 * 128, lb + 278528, 512, 128 };
            tab.e[idx++] = { dmlp_W1 + (size_t)l * 128 * 512, lb + 344064, 128, 512 };
            tab.e[idx++] = { dmlp_W2 + (size_t)l * 512 * 128, lb + 409600, 512, 128 };
            tab.e[idx++] = { emlp_W1 + (size_t)l * 384 * 128, lb + 475136, 384, 128 };
            tab.e[idx++] = { emlp_W2 + (size_t)l * 128 * 128, lb + 524288, 128, 128 };
            tab.e[idx++] = { emlp_W3 + (size_t)l * 128 * 128, lb + 540672, 128, 128 };
        }
    }

    auto gemm = [&](int M, int K, int nTile, int zDim,
                    const __nv_bfloat16* Ah, const __nv_bfloat16* Al, long long wOff,
                    const float* bias, float* Cp, __nv_bfloat16* CoH, __nv_bfloat16* CoL,
                    int ldc, int act, int feat, int osplit,
                    const float* aAv, const float* aAb) {
        dim3 g(nTile, (M + 127) / 128, zDim);
        gemm_tc<<<g, 256>>>(M, K, Ah, Al, pWh + wOff, pWl + wOff, bias, Cp, CoH, CoL, ldc,
                            act, feat, osplit, pNh, pNl, pEh, pEl, srcI, snkI, aAv, aAb);
    };

    // launches 1-5 (skipped by ncu -s 5), #6 = L0 score gemm (profiled)
    tsplit_k<<<dim3(256, 26), 256>>>(tab);                                    // 1
    embed_k<<<(Nn * 128 + 255) / 256, 256>>>(seq, seq_embed);                 // 2
    rbf_k<<<Ee, 128>>>(dist, edge_lin_W, edge_lin_b);                         // 3
    split_k<<<(Nn * 128 + 255) / 256, 256>>>(p_nodes, pNh, pNl, Nn * 128);    // 4
    split_k<<<(Ee * 128 + 255) / 256, 256>>>(p_eattr, pEh, pEl, Ee * 128);    // 5

    bool csrBuilt = false;
    for (int l = 0; l < 2; l++) {
        long long lb = (long long)l * WT_LAYER;
        // attention scores (launch #6 on l==0 -> profiled)
        gemm(Ee, Cc, 1, 4, nullptr, nullptr, lb + 0, aW_b + l * 512,
             p_scores, nullptr, nullptr, 0, 2, 1, 0, aA_W + l * 512, aA_b + l * 4);
        if (!csrBuilt) {
            zero_cnt_k<<<(Nn + 255) / 256, 256>>>();
            count_k<<<(Ee + 255) / 256, 256>>>(snkI);
            scan_k<<<1, 1024>>>();
            place_k<<<(Ee + 255) / 256, 256>>>(snkI);
            csrBuilt = true;
        }
        // node-message MLP (split chain)
        gemm(Ee, Cc, 1, 1, nullptr, nullptr, lb + 196608, nmlp_b1 + l * 128,
             nullptr, pB1h, pB1l, 128, 1, 1, 1, nullptr, nullptr);
        gemm(Ee, 128, 1, 1, pB1h, pB1l, lb + 245760, nmlp_b2 + l * 128,
             nullptr, pB2h, pB2l, 128, 1, 0, 1, nullptr, nullptr);
        gemm(Ee, 128, 1, 1, pB2h, pB2l, lb + 262144, nmlp_b3 + l * 128,
             p_nupd, nullptr, nullptr, 128, 0, 0, 0, nullptr, nullptr);
        // scatter softmax + aggregation -> split agg
        agg_k<<<Nn, 128>>>();
        // upd = agg @ aggr_W + b
        gemm(Nn, 512, 1, 1, pAgh, pAgl, lb + 278528, aggr_b + l * 128,
             p_upd, nullptr, nullptr, 128, 0, 0, 0, nullptr, nullptr);
        ln_k<<<Nn, 128>>>(p_nodes, p_upd, n1_g + l * 128, n1_b + l * 128, p_nodes);
        split_k<<<(Nn * 128 + 255) / 256, 256>>>(p_nodes, pNh, pNl, Nn * 128);
        // dense MLP
        gemm(Nn, 128, 4, 1, pNh, pNl, lb + 344064, dmlp_b1 + l * 512,
             nullptr, pB1h, pB1l, 512, 1, 0, 1, nullptr, nullptr);
        gemm(Nn, 512, 1, 1, pB1h, pB1l, lb + 409600, dmlp_b2 + l * 128,
             p_dense, nullptr, nullptr, 128, 0, 0, 0, nullptr, nullptr);
        ln_k<<<Nn, 128>>>(p_dense, p_upd, n1_g + l * 128, n1_b + l * 128, p_nodes);
        split_k<<<(Nn * 128 + 255) / 256, 256>>>(p_nodes, pNh, pNl, Nn * 128);
        // edge MLP
        gemm(Ee, Cc, 1, 1, nullptr, nullptr, lb + 475136, emlp_b1 + l * 128,
             nullptr, pB1h, pB1l, 128, 1, 1, 1, nullptr, nullptr);
        gemm(Ee, 128, 1, 1, pB1h, pB1l, lb + 524288, emlp_b2 + l * 128,
             nullptr, pB2h, pB2l, 128, 1, 0, 1, nullptr, nullptr);
        gemm(Ee, 128, 1, 1, pB2h, pB2l, lb + 540672, emlp_b3 + l * 128,
             p_nupd, nullptr, nullptr, 128, 0, 0, 0, nullptr, nullptr);
        ln_k<<<Ee, 128>>>(p_eattr, p_nupd, e_g + l * 128, e_b + l * 128, p_eattr);
        if (l == 0)
            split_k<<<(Ee * 128 + 255) / 256, 256>>>(p_eattr, pEh, pEl, Ee * 128);
    }

    long long tot = (long long)Nn * 128 + (long long)Ee * 128;
    out_k<<<(int)((tot + 255) / 256), 256>>>((float*)d_out);
}

// round 7
// speedup vs baseline: 2.0408x; 1.5507x over previous
#include <cuda_runtime.h>
#include <cuda_bf16.h>
#include <math.h>
#include <stdint.h>

#define Nn 6000
#define Ee 120000
#define Dd 128
#define Hh 4
#define Cc 384

// ---------------- scratch (device globals) ----------------
__device__ __align__(16) float g_nodes[Nn * Dd];
__device__ __align__(16) float g_eattr[Ee * Dd];
__device__ __align__(16) float g_nupd[Ee * Dd];
__device__ __align__(16) float g_scores[Ee * Hh];
__device__ __align__(16) float g_upd[Nn * Dd];
__device__ __align__(16) float g_dense[Nn * Dd];
__device__ __align__(16) __nv_bfloat16 g_nodesH[Nn * Dd], g_nodesL[Nn * Dd];
__device__ __align__(16) __nv_bfloat16 g_eatH[Ee * Dd], g_eatL[Ee * Dd];
__device__ __align__(16) __nv_bfloat16 g_b1H[Ee * Dd], g_b1L[Ee * Dd];
__device__ __align__(16) __nv_bfloat16 g_b2H[Ee * Dd], g_b2L[Ee * Dd];
__device__ __align__(16) __nv_bfloat16 g_aggH[Nn * 4 * Dd], g_aggL[Nn * 4 * Dd];
__device__ int g_cnt[Nn];
__device__ int g_off[Nn + 1];
__device__ int g_cur[Nn];
__device__ int g_csr[Ee];
#define WT_LAYER 557056
__device__ __align__(16) __nv_bfloat16 g_wTh[2 * WT_LAYER];
__device__ __align__(16) __nv_bfloat16 g_wTl[2 * WT_LAYER];

__device__ __forceinline__ float gelu_f(float x) {
    return 0.5f * x * (1.0f + erff(x * 0.70710678118654752f));
}
__device__ __forceinline__ uint32_t smem_u32(const void* p) {
    uint32_t a;
    asm("{ .reg .u64 t; cvta.to.shared.u64 t, %1; cvt.u32.u64 %0, t; }" : "=r"(a) : "l"(p));
    return a;
}
__device__ __forceinline__ void ldsm4(uint32_t* r, uint32_t addr) {
    asm volatile("ldmatrix.sync.aligned.m8n8.x4.shared.b16 {%0,%1,%2,%3}, [%4];"
                 : "=r"(r[0]), "=r"(r[1]), "=r"(r[2]), "=r"(r[3]) : "r"(addr));
}
__device__ __forceinline__ void mma16816(float* d, const uint32_t* a, const uint32_t* b) {
    asm volatile("mma.sync.aligned.m16n8k16.row.col.f32.bf16.bf16.f32 "
                 "{%0,%1,%2,%3}, {%4,%5,%6,%7}, {%8,%9}, {%0,%1,%2,%3};"
                 : "+f"(d[0]), "+f"(d[1]), "+f"(d[2]), "+f"(d[3])
                 : "r"(a[0]), "r"(a[1]), "r"(a[2]), "r"(a[3]), "r"(b[0]), "r"(b[1]));
}
__device__ __forceinline__ void split2(float x, __nv_bfloat16& h, __nv_bfloat16& l) {
    h = __float2bfloat16_rn(x);
    l = __float2bfloat16_rn(x - __bfloat162float(h));
}
__device__ __forceinline__ void cp16(uint32_t saddr, const void* g) {
    asm volatile("cp.async.ca.shared.global [%0], [%1], 16;" :: "r"(saddr), "l"(g));
}
#define CP_COMMIT() asm volatile("cp.async.commit_group;" ::: "memory")
#define CP_WAIT1()  asm volatile("cp.async.wait_group 1;" ::: "memory")
#define CP_WAIT0()  asm volatile("cp.async.wait_group 0;" ::: "memory")

// ---------------- HMMA GEMM, cp.async double-buffered ----------------
// SMEM layout (dynamic): per buf {Ah, Al, Bh, Bl} each 128 rows x 80B pitch (=10240B)
// buf stride 40960; part[128][2] floats at 81920. total 82944.
#define PITCH 80
#define ARR 10240
#define BUFSTR 40960
#define SM_PART 81920
#define SM_TOTAL 82944

__global__ void __launch_bounds__(256) gemm_tc(
    int M, int K,
    const __nv_bfloat16* __restrict__ AhG, const __nv_bfloat16* __restrict__ AlG,
    const __nv_bfloat16* __restrict__ BTh, const __nv_bfloat16* __restrict__ BTl,
    const float* __restrict__ bias,
    float* __restrict__ Cout,
    __nv_bfloat16* __restrict__ CoH, __nv_bfloat16* __restrict__ CoL, int ldc,
    int act, int featMode, int outSplit,
    const __nv_bfloat16* __restrict__ ndH, const __nv_bfloat16* __restrict__ ndL,
    const __nv_bfloat16* __restrict__ eaH, const __nv_bfloat16* __restrict__ eaL,
    const int* __restrict__ srcI, const int* __restrict__ snkI,
    const float* __restrict__ aAv, const float* __restrict__ aAb)
{
    extern __shared__ char sm[];
    const uint32_t sb = smem_u32(sm);
    const int tid = threadIdx.x, wid = tid >> 5, lane = tid & 31;
    const int m0 = blockIdx.y * 128, n0 = blockIdx.x * 128, z = blockIdx.z;
    if (act == 2) {
        size_t zo = (size_t)z * K * 128;
        BTh += zo; BTl += zo; bias += z * 128; aAv += z * 128;
    }
    const int mrow0 = (wid & 3) * 32;
    const int ncol0 = (wid >> 2) * 64;
    const int rowoff = ((lane >> 3) & 1) * 8 + (lane & 7);
    const int coloff = (lane >> 4) * 8;

    // per-thread load slots: A 2 groups (r,g), B 2 groups
    int ar[2], ag[2], br[2], bg[2];
#pragma unroll
    for (int it = 0; it < 2; ++it) {
        int idx = tid + it * 256;
        ar[it] = idx >> 2; ag[it] = (idx & 3) << 3;
        br[it] = idx >> 2; bg[it] = (idx & 3) << 3;
    }

    auto issue_chunk = [&](int c) {
        const uint32_t bb = sb + (c & 1) * BUFSTR;
        const int k0 = c << 5;
#pragma unroll
        for (int it = 0; it < 2; ++it) {
            int r = ar[it], g = ag[it];
            int mm = m0 + r; if (mm >= M) mm = M - 1;
            int kg = k0 + g;
            const __nv_bfloat16 *ph, *pl;
            if (!featMode) { ph = AhG + (size_t)mm * K + kg; pl = AlG + (size_t)mm * K + kg; }
            else if (kg < 128) { int s = srcI[mm]; ph = ndH + (size_t)s * 128 + kg; pl = ndL + (size_t)s * 128 + kg; }
            else if (kg < 256) { int s = snkI[mm]; ph = ndH + (size_t)s * 128 + (kg - 128); pl = ndL + (size_t)s * 128 + (kg - 128); }
            else { ph = eaH + (size_t)mm * 128 + (kg - 256); pl = eaL + (size_t)mm * 128 + (kg - 256); }
            uint32_t off = (uint32_t)(r * PITCH + g * 2);
            cp16(bb + off, ph);
            cp16(bb + ARR + off, pl);
        }
#pragma unroll
        for (int it = 0; it < 2; ++it) {
            int r = br[it], g = bg[it];
            size_t so = (size_t)(n0 + r) * K + k0 + g;
            uint32_t off = (uint32_t)(r * PITCH + g * 2);
            cp16(bb + 2 * ARR + off, BTh + so);
            cp16(bb + 3 * ARR + off, BTl + so);
        }
        CP_COMMIT();
    };

    float acc[2][8][4];
#pragma unroll
    for (int i = 0; i < 2; i++)
#pragma unroll
        for (int j = 0; j < 8; j++)
#pragma unroll
            for (int q = 0; q < 4; q++) acc[i][j][q] = 0.f;

    const int nCh = K >> 5;
    issue_chunk(0);
    for (int c = 0; c < nCh; ++c) {
        if (c + 1 < nCh) { issue_chunk(c + 1); CP_WAIT1(); }
        else CP_WAIT0();
        __syncthreads();
        const uint32_t bb = sb + (c & 1) * BUFSTR;
#pragma unroll
        for (int ks = 0; ks < 2; ++ks) {
            const uint32_t kb = (uint32_t)((ks * 16 + coloff) * 2);
            uint32_t ah[2][4], al[2][4];
#pragma unroll
            for (int ma = 0; ma < 2; ++ma) {
                uint32_t ro = (uint32_t)((mrow0 + ma * 16 + rowoff) * PITCH) + kb;
                ldsm4(ah[ma], bb + ro);
                ldsm4(al[ma], bb + ARR + ro);
            }
            uint32_t bh[8][2], bl[8][2];
#pragma unroll
            for (int ng = 0; ng < 4; ++ng) {
                uint32_t ro = (uint32_t)((ncol0 + ng * 16 + rowoff) * PITCH) + kb;
                uint32_t t[4];
                ldsm4(t, bb + 2 * ARR + ro);
                bh[2 * ng][0] = t[0]; bh[2 * ng][1] = t[2];
                bh[2 * ng + 1][0] = t[1]; bh[2 * ng + 1][1] = t[3];
                ldsm4(t, bb + 3 * ARR + ro);
                bl[2 * ng][0] = t[0]; bl[2 * ng][1] = t[2];
                bl[2 * ng + 1][0] = t[1]; bl[2 * ng + 1][1] = t[3];
            }
#pragma unroll
            for (int ma = 0; ma < 2; ++ma)
#pragma unroll
                for (int na = 0; na < 8; ++na) mma16816(acc[ma][na], ah[ma], bh[na]);
#pragma unroll
            for (int ma = 0; ma < 2; ++ma)
#pragma unroll
                for (int na = 0; na < 8; ++na) mma16816(acc[ma][na], ah[ma], bl[na]);
#pragma unroll
            for (int ma = 0; ma < 2; ++ma)
#pragma unroll
                for (int na = 0; na < 8; ++na) mma16816(acc[ma][na], al[ma], bh[na]);
        }
        __syncthreads();
    }

    // ---- epilogue ----
    float (*part)[2] = (float(*)[2])(sm + SM_PART);
    const int qr = lane >> 2, qc = (lane & 3) * 2;
    if (act == 2) {
        const int nh = wid >> 2;
        float s[2][2] = {{0.f, 0.f}, {0.f, 0.f}};
#pragma unroll
        for (int ma = 0; ma < 2; ++ma)
#pragma unroll
            for (int na = 0; na < 8; ++na) {
                int n = ncol0 + na * 8 + qc;
#pragma unroll
                for (int j = 0; j < 2; ++j) {
                    float v0 = acc[ma][na][j] + bias[n + j];
                    v0 = v0 > 0.f ? v0 : 0.2f * v0;
                    s[ma][0] += v0 * aAv[n + j];
                    float v1 = acc[ma][na][2 + j] + bias[n + j];
                    v1 = v1 > 0.f ? v1 : 0.2f * v1;
                    s[ma][1] += v1 * aAv[n + j];
                }
            }
#pragma unroll
        for (int ma = 0; ma < 2; ++ma)
#pragma unroll
            for (int g = 0; g < 2; ++g) {
                s[ma][g] += __shfl_xor_sync(0xffffffffu, s[ma][g], 1);
                s[ma][g] += __shfl_xor_sync(0xffffffffu, s[ma][g], 2);
            }
        if ((lane & 3) == 0) {
#pragma unroll
            for (int ma = 0; ma < 2; ++ma) {
                part[mrow0 + ma * 16 + qr][nh] = s[ma][0];
                part[mrow0 + ma * 16 + 8 + qr][nh] = s[ma][1];
            }
        }
        __syncthreads();
        if (tid < 128) {
            int m = m0 + tid;
            if (m < M) Cout[(size_t)m * 4 + z] = part[tid][0] + part[tid][1] + aAb[z];
        }
        return;
    }
#pragma unroll
    for (int ma = 0; ma < 2; ++ma) {
        int mA = m0 + mrow0 + ma * 16 + qr;
        int mB = mA + 8;
#pragma unroll
        for (int na = 0; na < 8; ++na) {
            int n = n0 + ncol0 + na * 8 + qc;
            float2 oA, oB;
            oA.x = acc[ma][na][0] + bias[n];
            oA.y = acc[ma][na][1] + bias[n + 1];
            oB.x = acc[ma][na][2] + bias[n];
            oB.y = acc[ma][na][3] + bias[n + 1];
            if (act == 1) {
                oA.x = gelu_f(oA.x); oA.y = gelu_f(oA.y);
                oB.x = gelu_f(oB.x); oB.y = gelu_f(oB.y);
            }
            if (outSplit) {
                __nv_bfloat16 h0, l0, h1, l1;
                if (mA < M) {
                    split2(oA.x, h0, l0); split2(oA.y, h1, l1);
                    *(uint32_t*)(CoH + (size_t)mA * ldc + n) =
                        ((uint32_t)__bfloat16_as_ushort(h1) << 16) | __bfloat16_as_ushort(h0);
                    *(uint32_t*)(CoL + (size_t)mA * ldc + n) =
                        ((uint32_t)__bfloat16_as_ushort(l1) << 16) | __bfloat16_as_ushort(l0);
                }
                if (mB < M) {
                    split2(oB.x, h0, l0); split2(oB.y, h1, l1);
                    *(uint32_t*)(CoH + (size_t)mB * ldc + n) =
                        ((uint32_t)__bfloat16_as_ushort(h1) << 16) | __bfloat16_as_ushort(h0);
                    *(uint32_t*)(CoL + (size_t)mB * ldc + n) =
                        ((uint32_t)__bfloat16_as_ushort(l1) << 16) | __bfloat16_as_ushort(l0);
                }
            } else {
                if (mA < M) *(float2*)(Cout + (size_t)mA * ldc + n) = oA;
                if (mB < M) *(float2*)(Cout + (size_t)mB * ldc + n) = oB;
            }
        }
    }
}

// ---------------- weight transpose + bf16 split ----------------
struct TEnt { const float* src; int dstOff; int K; int N; };
struct TTab { TEnt e[26]; };
__global__ void tsplit_k(TTab tab) {
    TEnt E = tab.e[blockIdx.y];
    int i = blockIdx.x * 256 + threadIdx.x;
    int total = E.K * E.N;
    if (i >= total) return;
    int k = i / E.N, n = i % E.N;
    float x = E.src[i];
    __nv_bfloat16 h, l;
    split2(x, h, l);
    g_wTh[E.dstOff + (size_t)n * E.K + k] = h;
    g_wTl[E.dstOff + (size_t)n * E.K + k] = l;
}

// ---------------- setup (write fp32 + split) ----------------
__global__ void embed_k(const int* __restrict__ seq, const float* __restrict__ emb) {
    int i = blockIdx.x * 256 + threadIdx.x;
    if (i < Nn * 128) {
        int nidx = i >> 7, d = i & 127;
        float x = emb[seq[nidx] * 128 + d];
        g_nodes[i] = x;
        __nv_bfloat16 h, l;
        split2(x, h, l);
        g_nodesH[i] = h; g_nodesL[i] = l;
    }
}
__global__ void rbf_k(const float* __restrict__ dist, const float* __restrict__ W,
                      const float* __restrict__ b) {
    __shared__ float r[16];
    int e = blockIdx.x;
    int t = threadIdx.x;
    if (t < 16) {
        float mu = 2.0f + (20.0f / 15.0f) * (float)t;
        float x = (dist[e] - mu) * (1.0f / 1.25f);
        r[t] = expf(-x * x) + 1e-8f;
    }
    __syncthreads();
    float s = b[t];
#pragma unroll
    for (int j = 0; j < 16; j++) s += r[j] * W[j * 128 + t];
    long long i = (long long)e * 128 + t;
    g_eattr[i] = s;
    __nv_bfloat16 h, l;
    split2(s, h, l);
    g_eatH[i] = h; g_eatL[i] = l;
}

// ---------------- CSR ----------------
__global__ void zero_cnt_k() {
    int i = blockIdx.x * 256 + threadIdx.x;
    if (i < Nn) g_cnt[i] = 0;
}
__global__ void count_k(const int* __restrict__ snk) {
    int e = blockIdx.x * 256 + threadIdx.x;
    if (e < Ee) atomicAdd(&g_cnt[snk[e]], 1);
}
__global__ void __launch_bounds__(1024) scan_k() {
    __shared__ int s[1024];
    int t = threadIdx.x;
    const int CH = (Nn + 1023) / 1024;
    int st = t * CH;
    int en = st + CH; if (en > Nn) en = Nn; if (st > Nn) st = Nn;
    int loc = 0;
    for (int i = st; i < en; i++) loc += g_cnt[i];
    s[t] = loc;
    __syncthreads();
    for (int d = 1; d < 1024; d <<= 1) {
        int v = (t >= d) ? s[t - d] : 0;
        __syncthreads();
        s[t] += v;
        __syncthreads();
    }
    int run = (t == 0) ? 0 : s[t - 1];
    for (int i = st; i < en; i++) {
        g_off[i] = run; g_cur[i] = run; run += g_cnt[i];
    }
    if (t == 1023) g_off[Nn] = s[1023];
}
__global__ void place_k(const int* __restrict__ snk) {
    int e = blockIdx.x * 256 + threadIdx.x;
    if (e < Ee) {
        int p = atomicAdd(&g_cur[snk[e]], 1);
        g_csr[p] = e;
    }
}

// ---------------- per-node softmax + aggregation ----------------
__global__ void __launch_bounds__(128) agg_k() {
    __shared__ float red[4][128];
    int n = blockIdx.x, t = threadIdx.x;
    int beg = g_off[n], end = g_off[n + 1];
    const float4* sc4 = (const float4*)g_scores;

    float mx[4] = {-1e30f, -1e30f, -1e30f, -1e30f};
    for (int i = beg + t; i < end; i += 128) {
        float4 s = sc4[g_csr[i]];
        mx[0] = fmaxf(mx[0], s.x); mx[1] = fmaxf(mx[1], s.y);
        mx[2] = fmaxf(mx[2], s.z); mx[3] = fmaxf(mx[3], s.w);
    }
#pragma unroll
    for (int h = 0; h < 4; h++) red[h][t] = mx[h];
    __syncthreads();
    for (int s = 64; s > 0; s >>= 1) {
        if (t < s)
#pragma unroll
            for (int h = 0; h < 4; h++) red[h][t] = fmaxf(red[h][t], red[h][t + s]);
        __syncthreads();
    }
    float mxf[4];
#pragma unroll
    for (int h = 0; h < 4; h++) mxf[h] = red[h][0];
    __syncthreads();

    float sm[4] = {0.f, 0.f, 0.f, 0.f};
    for (int i = beg + t; i < end; i += 128) {
        float4 s = sc4[g_csr[i]];
        sm[0] += expf(s.x - mxf[0]) + 1e-12f;
        sm[1] += expf(s.y - mxf[1]) + 1e-12f;
        sm[2] += expf(s.z - mxf[2]) + 1e-12f;
        sm[3] += expf(s.w - mxf[3]) + 1e-12f;
    }
#pragma unroll
    for (int h = 0; h < 4; h++) red[h][t] = sm[h];
    __syncthreads();
    for (int s = 64; s > 0; s >>= 1) {
        if (t < s)
#pragma unroll
            for (int h = 0; h < 4; h++) red[h][t] += red[h][t + s];
        __syncthreads();
    }
    float nrm[4];
#pragma unroll
    for (int h = 0; h < 4; h++) nrm[h] = red[h][0];

    float acc[4] = {0.f, 0.f, 0.f, 0.f};
    for (int i = beg; i < end; i++) {
        int e = g_csr[i];
        float4 s = sc4[e];
        float a0 = expf(s.x - mxf[0]) / nrm[0];
        float a1 = expf(s.y - mxf[1]) / nrm[1];
        float a2 = expf(s.z - mxf[2]) / nrm[2];
        float a3 = expf(s.w - mxf[3]) / nrm[3];
        float v = g_nupd[(long long)e * 128 + t];
        acc[0] += a0 * v; acc[1] += a1 * v; acc[2] += a2 * v; acc[3] += a3 * v;
    }
    long long base = (long long)n * 512;
#pragma unroll
    for (int h = 0; h < 4; h++) {
        __nv_bfloat16 hh, ll;
        split2(acc[h], hh, ll);
        g_aggH[base + h * 128 + t] = hh;
        g_aggL[base + h * 128 + t] = ll;
    }
}

// ---------------- LayerNorm (+ optional split out) ----------------
__global__ void __launch_bounds__(128) ln_k(const float* __restrict__ a,
                                            const float* __restrict__ r,
                                            const float* __restrict__ g,
                                            const float* __restrict__ b,
                                            float* __restrict__ out,
                                            __nv_bfloat16* __restrict__ oh,
                                            __nv_bfloat16* __restrict__ ol) {
    int row = blockIdx.x, t = threadIdx.x;
    __shared__ float sh[8];
    long long base = (long long)row * 128;
    float x = a[base + t] + r[base + t];
    float s = x;
#pragma unroll
    for (int o = 16; o; o >>= 1) s += __shfl_xor_sync(0xffffffffu, s, o);
    if ((t & 31) == 0) sh[t >> 5] = s;
    __syncthreads();
    float mean = (sh[0] + sh[1] + sh[2] + sh[3]) * (1.0f / 128.0f);
    float d = x - mean;
    float v = d * d;
#pragma unroll
    for (int o = 16; o; o >>= 1) v += __shfl_xor_sync(0xffffffffu, v, o);
    if ((t & 31) == 0) sh[4 + (t >> 5)] = v;
    __syncthreads();
    float var = (sh[4] + sh[5] + sh[6] + sh[7]) * (1.0f / 128.0f);
    float y = d * rsqrtf(var + 1e-5f) * g[t] + b[t];
    out[base + t] = y;
    if (oh) {
        __nv_bfloat16 hh, ll;
        split2(y, hh, ll);
        oh[base + t] = hh; ol[base + t] = ll;
    }
}

// ---------------- copy out ----------------
__global__ void out_k(float* __restrict__ out) {
    long long i = (long long)blockIdx.x * 256 + threadIdx.x;
    const long long nTot = (long long)Nn * 128;
    const long long tot = nTot + (long long)Ee * 128;
    if (i < nTot) out[i] = g_nodes[i];
    else if (i < tot) out[i] = g_eattr[i - nTot];
}

// ---------------- host ----------------
extern "C" void kernel_launch(void* const* d_in, const int* in_sizes, int n_in,
                              void* d_out, int out_size) {
    const int* seq = (const int*)d_in[0];
    const int* eidx = (const int*)d_in[1];
    const int* srcI = eidx;
    const int* snkI = eidx + Ee;
    const float* dist = (const float*)d_in[2];
    const float* seq_embed = (const float*)d_in[3];
    const float* edge_lin_W = (const float*)d_in[4];
    const float* edge_lin_b = (const float*)d_in[5];
    const float* aW_W = (const float*)d_in[6];
    const float* aW_b = (const float*)d_in[7];
    const float* aA_W = (const float*)d_in[8];
    const float* aA_b = (const float*)d_in[9];
    const float* nmlp_W1 = (const float*)d_in[10];
    const float* nmlp_b1 = (const float*)d_in[11];
    const float* nmlp_W2 = (const float*)d_in[12];
    const float* nmlp_b2 = (const float*)d_in[13];
    const float* nmlp_W3 = (const float*)d_in[14];
    const float* nmlp_b3 = (const float*)d_in[15];
    const float* dmlp_W1 = (const float*)d_in[16];
    const float* dmlp_b1 = (const float*)d_in[17];
    const float* dmlp_W2 = (const float*)d_in[18];
    const float* dmlp_b2 = (const float*)d_in[19];
    const float* emlp_W1 = (const float*)d_in[20];
    const float* emlp_b1 = (const float*)d_in[21];
    const float* emlp_W2 = (const float*)d_in[22];
    const float* emlp_b2 = (const float*)d_in[23];
    const float* emlp_W3 = (const float*)d_in[24];
    const float* emlp_b3 = (const float*)d_in[25];
    const float* aggr_W = (const float*)d_in[26];
    const float* aggr_b = (const float*)d_in[27];
    const float* n1_g = (const float*)d_in[28];
    const float* n1_b = (const float*)d_in[29];
    const float* e_g = (const float*)d_in[30];
    const float* e_b = (const float*)d_in[31];

    float *p_nodes, *p_eattr, *p_nupd, *p_scores, *p_upd, *p_dense;
    __nv_bfloat16 *pWh, *pWl, *pNh, *pNl, *pEh, *pEl, *pB1h, *pB1l, *pB2h, *pB2l, *pAgh, *pAgl;
    cudaGetSymbolAddress((void**)&p_nodes, g_nodes);
    cudaGetSymbolAddress((void**)&p_eattr, g_eattr);
    cudaGetSymbolAddress((void**)&p_nupd, g_nupd);
    cudaGetSymbolAddress((void**)&p_scores, g_scores);
    cudaGetSymbolAddress((void**)&p_upd, g_upd);
    cudaGetSymbolAddress((void**)&p_dense, g_dense);
    cudaGetSymbolAddress((void**)&pWh, g_wTh);
    cudaGetSymbolAddress((void**)&pWl, g_wTl);
    cudaGetSymbolAddress((void**)&pNh, g_nodesH);
    cudaGetSymbolAddress((void**)&pNl, g_nodesL);
    cudaGetSymbolAddress((void**)&pEh, g_eatH);
    cudaGetSymbolAddress((void**)&pEl, g_eatL);
    cudaGetSymbolAddress((void**)&pB1h, g_b1H);
    cudaGetSymbolAddress((void**)&pB1l, g_b1L);
    cudaGetSymbolAddress((void**)&pB2h, g_b2H);
    cudaGetSymbolAddress((void**)&pB2l, g_b2L);
    cudaGetSymbolAddress((void**)&pAgh, g_aggH);
    cudaGetSymbolAddress((void**)&pAgl, g_aggL);

    cudaFuncSetAttribute(gemm_tc, cudaFuncAttributeMaxDynamicSharedMemorySize, SM_TOTAL);

    TTab tab;
    {
        int idx = 0;
        for (int l = 0; l < 2; l++) {
            int lb = l * WT_LAYER;
            for (int h = 0; h < 4; h++)
                tab.e[idx++] = { aW_W + (size_t)(l * 4 + h) * 384 * 128, lb + h * 49152, 384, 128 };
            tab.e[idx++] = { nmlp_W1 + (size_t)l * 384 * 128, lb + 196608, 384, 128 };
            tab.e[idx++] = { nmlp_W2 + (size_t)l * 128 * 128, lb + 245760, 128, 128 };
            tab.e[idx++] = { nmlp_W3 + (size_t)l * 128 * 128, lb + 262144, 128, 128 };
            tab.e[idx++] = { aggr_W + (size_t)l * 512 * 128, lb + 278528, 512, 128 };
            tab.e[idx++] = { dmlp_W1 + (size_t)l * 128 * 512, lb + 344064, 128, 512 };
            tab.e[idx++] = { dmlp_W2 + (size_t)l * 512 * 128, lb + 409600, 512, 128 };
            tab.e[idx++] = { emlp_W1 + (size_t)l * 384 * 128, lb + 475136, 384, 128 };
            tab.e[idx++] = { emlp_W2 + (size_t)l * 128 * 128, lb + 524288, 128, 128 };
            tab.e[idx++] = { emlp_W3 + (size_t)l * 128 * 128, lb + 540672, 128, 128 };
        }
    }

    auto gemm = [&](int M, int K, int nTile, int zDim,
                    const __nv_bfloat16* Ah, const __nv_bfloat16* Al, long long wOff,
                    const float* bias, float* Cp, __nv_bfloat16* CoH, __nv_bfloat16* CoL,
                    int ldc, int act, int feat, int osplit,
                    const float* aAv, const float* aAb) {
        dim3 g(nTile, (M + 127) / 128, zDim);
        gemm_tc<<<g, 256, SM_TOTAL>>>(M, K, Ah, Al, pWh + wOff, pWl + wOff, bias, Cp, CoH, CoL, ldc,
                                      act, feat, osplit, pNh, pNl, pEh, pEl, srcI, snkI, aAv, aAb);
    };

    tsplit_k<<<dim3(256, 26), 256>>>(tab);                                    // 1
    embed_k<<<(Nn * 128 + 255) / 256, 256>>>(seq, seq_embed);                 // 2
    rbf_k<<<Ee, 128>>>(dist, edge_lin_W, edge_lin_b);                         // 3

    bool csrBuilt = false;
    for (int l = 0; l < 2; l++) {
        long long lb = (long long)l * WT_LAYER;
        // attention scores (launches 4-6 on l==0 are GEMMs -> profiled)
        gemm(Ee, Cc, 1, 4, nullptr, nullptr, lb + 0, aW_b + l * 512,
             p_scores, nullptr, nullptr, 0, 2, 1, 0, aA_W + l * 512, aA_b + l * 4);
        // node-message MLP
        gemm(Ee, Cc, 1, 1, nullptr, nullptr, lb + 196608, nmlp_b1 + l * 128,
             nullptr, pB1h, pB1l, 128, 1, 1, 1, nullptr, nullptr);
        gemm(Ee, 128, 1, 1, pB1h, pB1l, lb + 245760, nmlp_b2 + l * 128,
             nullptr, pB2h, pB2l, 128, 1, 0, 1, nullptr, nullptr);
        gemm(Ee, 128, 1, 1, pB2h, pB2l, lb + 262144, nmlp_b3 + l * 128,
             p_nupd, nullptr, nullptr, 128, 0, 0, 0, nullptr, nullptr);
        if (!csrBuilt) {
            zero_cnt_k<<<(Nn + 255) / 256, 256>>>();
            count_k<<<(Ee + 255) / 256, 256>>>(snkI);
            scan_k<<<1, 1024>>>();
            place_k<<<(Ee + 255) / 256, 256>>>(snkI);
            csrBuilt = true;
        }
        agg_k<<<Nn, 128>>>();
        gemm(Nn, 512, 1, 1, pAgh, pAgl, lb + 278528, aggr_b + l * 128,
             p_upd, nullptr, nullptr, 128, 0, 0, 0, nullptr, nullptr);
        ln_k<<<Nn, 128>>>(p_nodes, p_upd, n1_g + l * 128, n1_b + l * 128, p_nodes, pNh, pNl);
        gemm(Nn, 128, 4, 1, pNh, pNl, lb + 344064, dmlp_b1 + l * 512,
             nullptr, pB1h, pB1l, 512, 1, 0, 1, nullptr, nullptr);
        gemm(Nn, 512, 1, 1, pB1h, pB1l, lb + 409600, dmlp_b2 + l * 128,
             p_dense, nullptr, nullptr, 128, 0, 0, 0, nullptr, nullptr);
        ln_k<<<Nn, 128>>>(p_dense, p_upd, n1_g + l * 128, n1_b + l * 128, p_nodes, pNh, pNl);
        gemm(Ee, Cc, 1, 1, nullptr, nullptr, lb + 475136, emlp_b1 + l * 128,
             nullptr, pB1h, pB1l, 128, 1, 1, 1, nullptr, nullptr);
        gemm(Ee, 128, 1, 1, pB1h, pB1l, lb + 524288, emlp_b2 + l * 128,
             nullptr, pB2h, pB2l, 128, 1, 0, 1, nullptr, nullptr);
        gemm(Ee, 128, 1, 1, pB2h, pB2l, lb + 540672, emlp_b3 + l * 128,
             p_nupd, nullptr, nullptr, 128, 0, 0, 0, nullptr, nullptr);
        ln_k<<<Ee, 128>>>(p_eattr, p_nupd, e_g + l * 128, e_b + l * 128, p_eattr,
                          l == 0 ? pEh : nullptr, l == 0 ? pEl : nullptr);
    }

    long long tot = (long long)Nn * 128 + (long long)Ee * 128;
    out_k<<<(int)((tot + 255) / 256), 256>>>((float*)d_out);
}